// round 11
// baseline (speedup 1.0000x reference)
#include <cuda_runtime.h>
#include <cstdint>
#include <cstddef>

#define B_SZ 16384
#define D_SZ 2048
#define H_SZ 1024
#define HH   512
#define L_SZ 32
#define NROUNDS 32

// ---------------- scratch (device globals; no allocation allowed) ----------
__device__ float g_h1[(size_t)B_SZ * H_SZ];   // h1, later reused for h4
__device__ float g_h2[(size_t)B_SZ * HH];     // h2, later reused for h3
__device__ float g_z [(size_t)B_SZ * L_SZ];
__device__ float g_eps[(size_t)NROUNDS * B_SZ];
__device__ float g_u [(size_t)NROUNDS * B_SZ];

// ---------------- JAX threefry2x32 (partitionable semantics) ---------------
__device__ __forceinline__ uint2 tf2x32(uint32_t k0, uint32_t k1,
                                        uint32_t x0, uint32_t x1) {
  uint32_t ks2 = k0 ^ k1 ^ 0x1BD11BDAu;
#define TFR(r) { x0 += x1; x1 = (x1 << (r)) | (x1 >> (32 - (r))); x1 ^= x0; }
  x0 += k0; x1 += k1;
  TFR(13) TFR(15) TFR(26) TFR(6)
  x0 += k1;  x1 += ks2 + 1u;
  TFR(17) TFR(29) TFR(16) TFR(24)
  x0 += ks2; x1 += k0 + 2u;
  TFR(13) TFR(15) TFR(26) TFR(6)
  x0 += k0;  x1 += k1 + 3u;
  TFR(17) TFR(29) TFR(16) TFR(24)
  x0 += k1;  x1 += ks2 + 4u;
  TFR(13) TFR(15) TFR(26) TFR(6)
  x0 += ks2; x1 += k0 + 5u;
#undef TFR
  return make_uint2(x0, x1);
}

// uniform [0,1): mantissa-bits trick, exactly JAX's _uniform
__device__ __forceinline__ float u01f(uint32_t bits) {
  return __uint_as_float((bits >> 9) | 0x3f800000u) - 1.0f;
}

// XLA ErfInv32 (Giles polynomial) — no fma contraction
__device__ __forceinline__ float xla_erfinv(float x) {
  float t = __fmul_rn(x, x);
  float w = -log1pf(-t);
  float p;
  if (w < 5.0f) {
    w = __fadd_rn(w, -2.5f);
    p = 2.81022636e-08f;
    p = __fadd_rn(3.43273939e-07f, __fmul_rn(p, w));
    p = __fadd_rn(-3.5233877e-06f, __fmul_rn(p, w));
    p = __fadd_rn(-4.39150654e-06f, __fmul_rn(p, w));
    p = __fadd_rn(0.00021858087f, __fmul_rn(p, w));
    p = __fadd_rn(-0.00125372503f, __fmul_rn(p, w));
    p = __fadd_rn(-0.00417768164f, __fmul_rn(p, w));
    p = __fadd_rn(0.246640727f, __fmul_rn(p, w));
    p = __fadd_rn(1.50140941f, __fmul_rn(p, w));
  } else {
    w = __fadd_rn(sqrtf(w), -3.0f);
    p = -0.000200214257f;
    p = __fadd_rn(0.000100950558f, __fmul_rn(p, w));
    p = __fadd_rn(0.00134934322f, __fmul_rn(p, w));
    p = __fadd_rn(-0.00367342844f, __fmul_rn(p, w));
    p = __fadd_rn(0.00573950773f, __fmul_rn(p, w));
    p = __fadd_rn(-0.0076224613f, __fmul_rn(p, w));
    p = __fadd_rn(0.00943887047f, __fmul_rn(p, w));
    p = __fadd_rn(1.00167406f, __fmul_rn(p, w));
    p = __fadd_rn(2.83297682f, __fmul_rn(p, w));
  }
  return __fmul_rn(p, x);
}

// jax.random.normal scalar from 32 random bits
__device__ __forceinline__ float jax_normal_from_bits(uint32_t bits) {
  const float lo = -0.99999994f;                 // nextafterf(-1,0)
  float f = u01f(bits);
  float uu = __fadd_rn(__fmul_rn(f, 2.0f), lo);  // (hi-lo) rounds to exactly 2.0f
  uu = fmaxf(lo, uu);
  return __fmul_rn(1.41421356f, xla_erfinv(uu));
}

// JAX _gamma_one (log_space=True) for alpha = 15.5 (boost inactive).
__device__ float loggamma15p5(uint2 ekey) {
  const float d = __fadd_rn(15.5f, -0.33333334f);
  const float c = __fdiv_rn(0.33333334f, sqrtf(d));
  uint2 key = tf2x32(ekey.x, ekey.y, 0u, 0u);    // key, subkey = split(key)
  float V = 1.0f;
  for (int it = 0; it < 256; it++) {
    uint2 nk = tf2x32(key.x, key.y, 0u, 0u);     // split3: new key
    uint2 xk = tf2x32(key.x, key.y, 0u, 1u);     //         x_key
    uint2 Uk = tf2x32(key.x, key.y, 0u, 2u);     //         U_key
    key = nk;
    float xn = 0.0f, v = -1.0f;
    uint2 kx = xk;
    for (int jt = 0; jt < 256; jt++) {           // inner: while v <= 0
      uint2 nk2 = tf2x32(kx.x, kx.y, 0u, 0u);
      uint2 sub = tf2x32(kx.x, kx.y, 0u, 1u);
      kx = nk2;
      uint2 ob = tf2x32(sub.x, sub.y, 0u, 0u);
      xn = jax_normal_from_bits(ob.x ^ ob.y);
      v = __fadd_rn(1.0f, __fmul_rn(xn, c));
      if (!(v <= 0.0f)) break;
    }
    float X = __fmul_rn(xn, xn);
    V = __fmul_rn(__fmul_rn(v, v), v);
    uint2 ou = tf2x32(Uk.x, Uk.y, 0u, 0u);
    float U = u01f(ou.x ^ ou.y);
    bool c1 = U >= __fsub_rn(1.0f, __fmul_rn(0.0331f, __fmul_rn(X, X)));
    float rhs = __fadd_rn(__fmul_rn(X, 0.5f),
                          __fmul_rn(d, __fadd_rn(__fsub_rn(1.0f, V), logf(V))));
    bool c2 = logf(U) >= rhs;
    if (!(c1 && c2)) break;                      // accepted
  }
  return __fadd_rn(logf(d), logf(V));
}

// ---------------- RNG kernel: eps (beta) and u per (round, element) --------
__global__ void __launch_bounds__(256)
rng_kernel(float* __restrict__ eps_arr, float* __restrict__ u_arr) {
  int t = blockIdx.x * blockDim.x + threadIdx.x;
  if (t >= NROUNDS * B_SZ) return;
  int r = t >> 14, i = t & 16383;
  // key(42) = (0,42); split -> (k_rounds, k_tan)
  uint2 k_rounds = tf2x32(0u, 42u, 0u, 0u);
  uint2 rk = tf2x32(k_rounds.x, k_rounds.y, 0u, (uint32_t)r);  // round_keys[r]
  uint2 k1 = tf2x32(rk.x, rk.y, 0u, 0u);
  uint2 k2 = tf2x32(rk.x, rk.y, 0u, 1u);
  // beta: key_a, key_b = split(k1); per-element keys = split(key_x, 16384)[i]
  uint2 key_a = tf2x32(k1.x, k1.y, 0u, 0u);
  uint2 key_b = tf2x32(k1.x, k1.y, 0u, 1u);
  uint2 ka = tf2x32(key_a.x, key_a.y, 0u, (uint32_t)i);
  uint2 kb = tf2x32(key_b.x, key_b.y, 0u, (uint32_t)i);
  float lga = loggamma15p5(ka);
  float lgb = loggamma15p5(kb);
  float mx = fmaxf(lga, lgb);
  float ga = expf(__fsub_rn(lga, mx));
  float gb = expf(__fsub_rn(lgb, mx));
  eps_arr[t] = __fdiv_rn(ga, __fadd_rn(ga, gb));
  uint2 ou = tf2x32(k2.x, k2.y, 0u, (uint32_t)i);
  u_arr[t] = u01f(ou.x ^ ou.y);
}

// ---------------- SGEMM NT: C[M,N] = act(A[M,K] @ B[N,K]^T + bias) ---------
template<bool RELU>
__global__ void __launch_bounds__(256)
sgemm_nt(const float* __restrict__ A, const float* __restrict__ Bw,
         const float* __restrict__ bias, float* __restrict__ C,
         int M, int N, int K) {
  __shared__ float As[16][132];
  __shared__ float Bs[16][132];
  const int tid = threadIdx.x;
  const int tx = tid & 15, ty = tid >> 4;
  const int m0 = blockIdx.y << 7, n0 = blockIdx.x << 7;
  const float* Ab = A + (size_t)m0 * K;
  const float* Bb = Bw + (size_t)n0 * K;
  const int lrow = tid >> 2;   // 0..63
  const int seg  = tid & 3;    // 0..3
  float acc[8][8];
#pragma unroll
  for (int i = 0; i < 8; i++)
#pragma unroll
    for (int j = 0; j < 8; j++) acc[i][j] = 0.0f;

  for (int k0 = 0; k0 < K; k0 += 16) {
#pragma unroll
    for (int s = 0; s < 2; s++) {
      int r = lrow + s * 64;
      float4 av = *(const float4*)(Ab + (size_t)r * K + k0 + seg * 4);
      As[seg*4+0][r] = av.x; As[seg*4+1][r] = av.y;
      As[seg*4+2][r] = av.z; As[seg*4+3][r] = av.w;
      float4 bv = *(const float4*)(Bb + (size_t)r * K + k0 + seg * 4);
      Bs[seg*4+0][r] = bv.x; Bs[seg*4+1][r] = bv.y;
      Bs[seg*4+2][r] = bv.z; Bs[seg*4+3][r] = bv.w;
    }
    __syncthreads();
#pragma unroll
    for (int kk = 0; kk < 16; kk++) {
      float ar[8], br[8];
#pragma unroll
      for (int i = 0; i < 8; i++) ar[i] = As[kk][ty*8 + i];
#pragma unroll
      for (int j = 0; j < 8; j++) br[j] = Bs[kk][tx*8 + j];
#pragma unroll
      for (int i = 0; i < 8; i++)
#pragma unroll
        for (int j = 0; j < 8; j++)
          acc[i][j] += ar[i] * br[j];
    }
    __syncthreads();
  }
#pragma unroll
  for (int i = 0; i < 8; i++) {
    int m = m0 + ty*8 + i;
    float* crow = C + (size_t)m * N + n0 + tx*8;
#pragma unroll
    for (int j = 0; j < 8; j++) {
      float v = acc[i][j] + bias[n0 + tx*8 + j];
      if (RELU) v = fmaxf(v, 0.0f);
      crow[j] = v;
    }
  }
}

// ---------------- fused mu / kappa head (N=33, K=512) ----------------------
__global__ void __launch_bounds__(128)
mukappa_kernel(const float* __restrict__ h2, const float* __restrict__ Wmu,
               const float* __restrict__ bmu, const float* __restrict__ Wk,
               const float* __restrict__ bk, float* __restrict__ mu_out,
               float* __restrict__ kap_out) {
  __shared__ float hs[HH];
  __shared__ float outv[33];
  const int r = blockIdx.x;
  const int tid = threadIdx.x;
  ((float4*)hs)[tid] = ((const float4*)(h2 + (size_t)r * HH))[tid];
  __syncthreads();
  const int w = tid >> 5, lane = tid & 31;
  for (int j = w; j < 33; j += 4) {
    const float* wr = (j < 32) ? (Wmu + (size_t)j * HH) : Wk;
    float s = 0.0f;
#pragma unroll 4
    for (int t = lane; t < HH; t += 32) s += hs[t] * wr[t];
#pragma unroll
    for (int off = 16; off; off >>= 1) s += __shfl_down_sync(0xffffffffu, s, off);
    if (lane == 0) outv[j] = s + ((j < 32) ? bmu[j] : bk[0]);
  }
  __syncthreads();
  if (tid < 32) {
    float m = outv[tid];
    float ss = m * m;
#pragma unroll
    for (int off = 16; off; off >>= 1) ss += __shfl_xor_sync(0xffffffffu, ss, off);
    float nf = sqrtf(ss) + 1e-8f;
    mu_out[(size_t)r * 32 + tid] = m / nf;
    if (tid == 0) {
      float xx = outv[32];
      float sp = fmaxf(xx, 0.0f) + log1pf(expf(-fabsf(xx)));  // logaddexp(x,0)
      kap_out[r] = sp + 1.0f;
    }
  }
}

// ---------------- vMF: Wood scan + tangent normals + Householder -----------
__global__ void __launch_bounds__(256)
vmf_z_kernel(const float* __restrict__ mu, const float* __restrict__ kap,
             const float* __restrict__ eps_arr, const float* __restrict__ u_arr,
             float* __restrict__ z) {
  int i = blockIdx.x * blockDim.x + threadIdx.x;
  if (i >= B_SZ) return;
  float k = kap[i];
  float sq = sqrtf(__fadd_rn(__fmul_rn(__fmul_rn(4.0f, k), k), 961.0f));
  float b  = __fdiv_rn(__fadd_rn(__fmul_rn(-2.0f, k), sq), 31.0f);
  float a  = __fdiv_rn(__fadd_rn(__fadd_rn(31.0f, __fmul_rn(2.0f, k)), sq), 4.0f);
  float d  = __fsub_rn(__fdiv_rn(__fmul_rn(__fmul_rn(4.0f, a), b), __fadd_rn(1.0f, b)),
                       __fmul_rn(31.0f, logf(31.0f)));
  float omb = __fsub_rn(1.0f, b), opb = __fadd_rn(1.0f, b);
  float ab2 = __fmul_rn(__fmul_rn(2.0f, a), b);
  float w = 0.0f; bool acc = false;
  for (int r = 0; r < NROUNDS; r++) {
    float eps = eps_arr[r * B_SZ + i];
    float u   = u_arr[r * B_SZ + i];
    float denom = __fsub_rn(1.0f, __fmul_rn(omb, eps));
    float wp = __fdiv_rn(__fsub_rn(1.0f, __fmul_rn(opb, eps)), denom);
    float t  = __fdiv_rn(ab2, denom);
    bool ok = __fadd_rn(__fsub_rn(__fmul_rn(31.0f, logf(t)), t), d)
              >= logf(__fadd_rn(u, 1e-20f));
    w = acc ? w : wp;
    acc = acc || ok;
  }
  w = fminf(fmaxf(w, -0.99999988f), 0.99999988f);

  // tangent normals v[31], element (i,j) counter = i*31 + j under k_tan
  uint2 kt = tf2x32(0u, 42u, 0u, 1u);
  float v[31]; float ss = 0.0f;
#pragma unroll
  for (int j = 0; j < 31; j++) {
    uint2 o = tf2x32(kt.x, kt.y, 0u, (uint32_t)(i * 31 + j));
    float xn = jax_normal_from_bits(o.x ^ o.y);
    v[j] = xn; ss += xn * xn;
  }
  float nf = sqrtf(ss) + 1e-12f;
  float s = sqrtf(__fsub_rn(1.0f, __fmul_rn(w, w)));

  const float* mrow = mu + (size_t)i * 32;
  float mloc[32];
#pragma unroll
  for (int c = 0; c < 32; c++) mloc[c] = mrow[c];
  float un2 = 0.0f;
#pragma unroll
  for (int c = 0; c < 32; c++) {
    float uh = ((c == 0) ? 1.0f : 0.0f) - mloc[c];
    un2 += uh * uh;
  }
  float unf = sqrtf(un2) + 1e-8f;
  float dot = 0.0f;
#pragma unroll
  for (int c = 0; c < 32; c++) {
    float ze = (c == 0) ? w : s * (v[c - 1] / nf);
    float uh = (((c == 0) ? 1.0f : 0.0f) - mloc[c]) / unf;
    dot += ze * uh;
  }
  float td = 2.0f * dot;
#pragma unroll
  for (int c = 0; c < 32; c++) {
    float ze = (c == 0) ? w : s * (v[c - 1] / nf);
    float uh = (((c == 0) ? 1.0f : 0.0f) - mloc[c]) / unf;
    z[(size_t)i * 32 + c] = ze - td * uh;
  }
}

// ---------------- launch ----------------------------------------------------
extern "C" void kernel_launch(void* const* d_in, const int* in_sizes, int n_in,
                              void* d_out, int out_size) {
  const float* x   = (const float*)d_in[0];
  const float* W1  = (const float*)d_in[1];
  const float* b1  = (const float*)d_in[2];
  const float* W2  = (const float*)d_in[3];
  const float* b2  = (const float*)d_in[4];
  const float* Wmu = (const float*)d_in[5];
  const float* bmu = (const float*)d_in[6];
  const float* Wk  = (const float*)d_in[7];
  const float* bk  = (const float*)d_in[8];
  const float* W3  = (const float*)d_in[9];
  const float* b3  = (const float*)d_in[10];
  const float* W4  = (const float*)d_in[11];
  const float* b4  = (const float*)d_in[12];
  const float* W5  = (const float*)d_in[13];
  const float* b5  = (const float*)d_in[14];

  float* out = (float*)d_out;
  float* x_recon = out;                                   // [B, D]
  float* mu_out  = out + (size_t)B_SZ * D_SZ;             // [B, L]
  float* kap_out = mu_out + (size_t)B_SZ * L_SZ;          // [B, 1]

  float *h1, *h2, *zbuf, *epsb, *ub;
  cudaGetSymbolAddress((void**)&h1,   g_h1);
  cudaGetSymbolAddress((void**)&h2,   g_h2);
  cudaGetSymbolAddress((void**)&zbuf, g_z);
  cudaGetSymbolAddress((void**)&epsb, g_eps);
  cudaGetSymbolAddress((void**)&ub,   g_u);

  // RNG (independent of everything)
  rng_kernel<<<(NROUNDS * B_SZ) / 256, 256>>>(epsb, ub);

  // encoder
  sgemm_nt<true><<<dim3(H_SZ/128, B_SZ/128), 256>>>(x,  W1, b1, h1, B_SZ, H_SZ, D_SZ);
  sgemm_nt<true><<<dim3(HH/128,   B_SZ/128), 256>>>(h1, W2, b2, h2, B_SZ, HH,  H_SZ);

  // heads
  mukappa_kernel<<<B_SZ, 128>>>(h2, Wmu, bmu, Wk, bk, mu_out, kap_out);

  // sampling
  vmf_z_kernel<<<B_SZ/256, 256>>>(mu_out, kap_out, epsb, ub, zbuf);

  // decoder (reuse h2 for h3, h1 for h4)
  sgemm_nt<true><<<dim3(HH/128,   B_SZ/128), 256>>>(zbuf, W3, b3, h2, B_SZ, HH,  L_SZ);
  sgemm_nt<true><<<dim3(H_SZ/128, B_SZ/128), 256>>>(h2,   W4, b4, h1, B_SZ, H_SZ, HH);
  sgemm_nt<false><<<dim3(D_SZ/128, B_SZ/128), 256>>>(h1,  W5, b5, x_recon, B_SZ, D_SZ, H_SZ);
}

// round 12
// speedup vs baseline: 1.8221x; 1.8221x over previous
#include <cuda_runtime.h>
#include <cuda_bf16.h>
#include <cstdint>
#include <cstddef>

#define B_SZ 16384
#define D_SZ 2048
#define H_SZ 1024
#define HH   512
#define L_SZ 32
#define NROUNDS 32

// ---------------- scratch (device globals; no allocation allowed) ----------
__device__ float g_h2[(size_t)B_SZ * HH];     // h2 fp32, later reused for h3 fp32
__device__ float g_z [(size_t)B_SZ * L_SZ];
__device__ float g_eps[(size_t)NROUNDS * B_SZ];
__device__ float g_u [(size_t)NROUNDS * B_SZ];

// bf16 split planes (plane p at offset p*planeElems)
__device__ __nv_bfloat16 g_xa [3 * (size_t)B_SZ * D_SZ];
__device__ __nv_bfloat16 g_h1p[3 * (size_t)B_SZ * H_SZ];
__device__ __nv_bfloat16 g_h3p[2 * (size_t)B_SZ * HH];
__device__ __nv_bfloat16 g_h4p[2 * (size_t)B_SZ * H_SZ];
__device__ __nv_bfloat16 g_W1p[3 * (size_t)H_SZ * D_SZ];
__device__ __nv_bfloat16 g_W2p[3 * (size_t)HH * H_SZ];
__device__ __nv_bfloat16 g_W4p[2 * (size_t)H_SZ * HH];
__device__ __nv_bfloat16 g_W5p[2 * (size_t)D_SZ * H_SZ];

// ---------------- JAX threefry2x32 (partitionable semantics) ---------------
__device__ __forceinline__ uint2 tf2x32(uint32_t k0, uint32_t k1,
                                        uint32_t x0, uint32_t x1) {
  uint32_t ks2 = k0 ^ k1 ^ 0x1BD11BDAu;
#define TFR(r) { x0 += x1; x1 = (x1 << (r)) | (x1 >> (32 - (r))); x1 ^= x0; }
  x0 += k0; x1 += k1;
  TFR(13) TFR(15) TFR(26) TFR(6)
  x0 += k1;  x1 += ks2 + 1u;
  TFR(17) TFR(29) TFR(16) TFR(24)
  x0 += ks2; x1 += k0 + 2u;
  TFR(13) TFR(15) TFR(26) TFR(6)
  x0 += k0;  x1 += k1 + 3u;
  TFR(17) TFR(29) TFR(16) TFR(24)
  x0 += k1;  x1 += ks2 + 4u;
  TFR(13) TFR(15) TFR(26) TFR(6)
  x0 += ks2; x1 += k0 + 5u;
#undef TFR
  return make_uint2(x0, x1);
}

__device__ __forceinline__ float u01f(uint32_t bits) {
  return __uint_as_float((bits >> 9) | 0x3f800000u) - 1.0f;
}

__device__ __forceinline__ float xla_erfinv(float x) {
  float t = __fmul_rn(x, x);
  float w = -log1pf(-t);
  float p;
  if (w < 5.0f) {
    w = __fadd_rn(w, -2.5f);
    p = 2.81022636e-08f;
    p = __fadd_rn(3.43273939e-07f, __fmul_rn(p, w));
    p = __fadd_rn(-3.5233877e-06f, __fmul_rn(p, w));
    p = __fadd_rn(-4.39150654e-06f, __fmul_rn(p, w));
    p = __fadd_rn(0.00021858087f, __fmul_rn(p, w));
    p = __fadd_rn(-0.00125372503f, __fmul_rn(p, w));
    p = __fadd_rn(-0.00417768164f, __fmul_rn(p, w));
    p = __fadd_rn(0.246640727f, __fmul_rn(p, w));
    p = __fadd_rn(1.50140941f, __fmul_rn(p, w));
  } else {
    w = __fadd_rn(sqrtf(w), -3.0f);
    p = -0.000200214257f;
    p = __fadd_rn(0.000100950558f, __fmul_rn(p, w));
    p = __fadd_rn(0.00134934322f, __fmul_rn(p, w));
    p = __fadd_rn(-0.00367342844f, __fmul_rn(p, w));
    p = __fadd_rn(0.00573950773f, __fmul_rn(p, w));
    p = __fadd_rn(-0.0076224613f, __fmul_rn(p, w));
    p = __fadd_rn(0.00943887047f, __fmul_rn(p, w));
    p = __fadd_rn(1.00167406f, __fmul_rn(p, w));
    p = __fadd_rn(2.83297682f, __fmul_rn(p, w));
  }
  return __fmul_rn(p, x);
}

__device__ __forceinline__ float jax_normal_from_bits(uint32_t bits) {
  const float lo = -0.99999994f;
  float f = u01f(bits);
  float uu = __fadd_rn(__fmul_rn(f, 2.0f), lo);
  uu = fmaxf(lo, uu);
  return __fmul_rn(1.41421356f, xla_erfinv(uu));
}

__device__ float loggamma15p5(uint2 ekey) {
  const float d = __fadd_rn(15.5f, -0.33333334f);
  const float c = __fdiv_rn(0.33333334f, sqrtf(d));
  uint2 key = tf2x32(ekey.x, ekey.y, 0u, 0u);
  float V = 1.0f;
  for (int it = 0; it < 256; it++) {
    uint2 nk = tf2x32(key.x, key.y, 0u, 0u);
    uint2 xk = tf2x32(key.x, key.y, 0u, 1u);
    uint2 Uk = tf2x32(key.x, key.y, 0u, 2u);
    key = nk;
    float xn = 0.0f, v = -1.0f;
    uint2 kx = xk;
    for (int jt = 0; jt < 256; jt++) {
      uint2 nk2 = tf2x32(kx.x, kx.y, 0u, 0u);
      uint2 sub = tf2x32(kx.x, kx.y, 0u, 1u);
      kx = nk2;
      uint2 ob = tf2x32(sub.x, sub.y, 0u, 0u);
      xn = jax_normal_from_bits(ob.x ^ ob.y);
      v = __fadd_rn(1.0f, __fmul_rn(xn, c));
      if (!(v <= 0.0f)) break;
    }
    float X = __fmul_rn(xn, xn);
    V = __fmul_rn(__fmul_rn(v, v), v);
    uint2 ou = tf2x32(Uk.x, Uk.y, 0u, 0u);
    float U = u01f(ou.x ^ ou.y);
    bool c1 = U >= __fsub_rn(1.0f, __fmul_rn(0.0331f, __fmul_rn(X, X)));
    float rhs = __fadd_rn(__fmul_rn(X, 0.5f),
                          __fmul_rn(d, __fadd_rn(__fsub_rn(1.0f, V), logf(V))));
    bool c2 = logf(U) >= rhs;
    if (!(c1 && c2)) break;
  }
  return __fadd_rn(logf(d), logf(V));
}

__global__ void __launch_bounds__(256)
rng_kernel(float* __restrict__ eps_arr, float* __restrict__ u_arr) {
  int t = blockIdx.x * blockDim.x + threadIdx.x;
  if (t >= NROUNDS * B_SZ) return;
  int r = t >> 14, i = t & 16383;
  uint2 k_rounds = tf2x32(0u, 42u, 0u, 0u);
  uint2 rk = tf2x32(k_rounds.x, k_rounds.y, 0u, (uint32_t)r);
  uint2 k1 = tf2x32(rk.x, rk.y, 0u, 0u);
  uint2 k2 = tf2x32(rk.x, rk.y, 0u, 1u);
  uint2 key_a = tf2x32(k1.x, k1.y, 0u, 0u);
  uint2 key_b = tf2x32(k1.x, k1.y, 0u, 1u);
  uint2 ka = tf2x32(key_a.x, key_a.y, 0u, (uint32_t)i);
  uint2 kb = tf2x32(key_b.x, key_b.y, 0u, (uint32_t)i);
  float lga = loggamma15p5(ka);
  float lgb = loggamma15p5(kb);
  float mx = fmaxf(lga, lgb);
  float ga = expf(__fsub_rn(lga, mx));
  float gb = expf(__fsub_rn(lgb, mx));
  eps_arr[t] = __fdiv_rn(ga, __fadd_rn(ga, gb));
  uint2 ou = tf2x32(k2.x, k2.y, 0u, (uint32_t)i);
  u_arr[t] = u01f(ou.x ^ ou.y);
}

// ---------------- bf16 split kernels ---------------------------------------
__global__ void __launch_bounds__(256)
split_kernel(const float* __restrict__ in, __nv_bfloat16* __restrict__ p1,
             __nv_bfloat16* __restrict__ p2, __nv_bfloat16* __restrict__ p3,
             size_t n) {
  size_t i = (size_t)blockIdx.x * 256 + threadIdx.x;
  if (i >= n) return;
  float v = in[i];
  __nv_bfloat16 b1 = __float2bfloat16_rn(v);
  float r1 = v - __bfloat162float(b1);
  __nv_bfloat16 b2 = __float2bfloat16_rn(r1);
  p1[i] = b1; p2[i] = b2;
  if (p3) {
    float r2 = r1 - __bfloat162float(b2);
    p3[i] = __float2bfloat16_rn(r2);
  }
}

// ---------------- tensor-core split GEMM -----------------------------------
// C[M,N] = act(sum_planes A@B^T + bias). A planes [M,K], B planes [N,K].
// 128x128 CTA tile, 8 warps of 64x32, KC=32, double-buffered cp.async.
__device__ __forceinline__ void mma16816(float* d, const uint32_t* a,
                                         const uint32_t* b) {
  asm volatile(
      "mma.sync.aligned.m16n8k16.row.col.f32.bf16.bf16.f32 "
      "{%0,%1,%2,%3},{%4,%5,%6,%7},{%8,%9},{%0,%1,%2,%3};"
      : "+f"(d[0]), "+f"(d[1]), "+f"(d[2]), "+f"(d[3])
      : "r"(a[0]), "r"(a[1]), "r"(a[2]), "r"(a[3]), "r"(b[0]), "r"(b[1]));
}

template <int NP, int NPROD, bool RELU, int NOUT>
__global__ void __launch_bounds__(256, 1)
mma_gemm(const __nv_bfloat16* __restrict__ A1, const __nv_bfloat16* __restrict__ A2,
         const __nv_bfloat16* __restrict__ A3,
         const __nv_bfloat16* __restrict__ B1, const __nv_bfloat16* __restrict__ B2,
         const __nv_bfloat16* __restrict__ B3,
         const float* __restrict__ bias,
         float* __restrict__ Cf,
         __nv_bfloat16* __restrict__ O1, __nv_bfloat16* __restrict__ O2,
         __nv_bfloat16* __restrict__ O3,
         int M, int N, int K) {
  extern __shared__ char smem[];
  constexpr int PLANES = 2 * NP;
  constexpr int PLANE_BYTES = 128 * 64;               // 128 rows x 32 bf16
  constexpr int STAGE_BYTES = PLANES * PLANE_BYTES;
  const int tid = threadIdx.x;
  const int wid = tid >> 5, lane = tid & 31;
  const int wm = wid >> 2, wn = wid & 3;              // 2 x 4 warps
  const int g = lane >> 2, t = lane & 3;
  const int m0 = blockIdx.y << 7, n0 = blockIdx.x << 7;
  const __nv_bfloat16* Ap[3] = {A1, A2, A3};
  const __nv_bfloat16* Bp[3] = {B1, B2, B3};
  uint32_t sbase = (uint32_t)__cvta_generic_to_shared(smem);

  float acc[4][4][4];
#pragma unroll
  for (int i = 0; i < 4; i++)
#pragma unroll
    for (int j = 0; j < 4; j++)
#pragma unroll
      for (int r = 0; r < 4; r++) acc[i][j][r] = 0.0f;

  const int KT = K >> 5;

#define ISSUE_STAGE(KT_IDX, STAGE)                                            \
  {                                                                           \
    int k0_ = (KT_IDX) << 5;                                                  \
    _Pragma("unroll")                                                         \
    for (int pl = 0; pl < PLANES; pl++) {                                     \
      const __nv_bfloat16* bptr = (pl < NP) ? Ap[pl] : Bp[pl - NP];           \
      int roff = (pl < NP) ? m0 : n0;                                         \
      _Pragma("unroll")                                                       \
      for (int h = 0; h < 2; h++) {                                           \
        int c = tid + h * 256;                                                \
        int row = c >> 2, seg = c & 3;                                        \
        const __nv_bfloat16* src =                                            \
            bptr + (size_t)(roff + row) * K + k0_ + seg * 8;                  \
        uint32_t off = (uint32_t)(row * 64 + seg * 16);                       \
        off ^= (off >> 3) & 0x30;                                             \
        uint32_t dst = sbase + (STAGE) * STAGE_BYTES + pl * PLANE_BYTES + off;\
        asm volatile("cp.async.cg.shared.global [%0], [%1], 16;\n" ::         \
                         "r"(dst), "l"(src));                                 \
      }                                                                       \
    }                                                                         \
  }

  ISSUE_STAGE(0, 0);
  asm volatile("cp.async.commit_group;\n");
  if (KT > 1) ISSUE_STAGE(1, 1);
  asm volatile("cp.async.commit_group;\n");

  constexpr int PAi[6] = {0, 0, 1, 1, 0, 2};
  constexpr int PBi[6] = {0, 1, 0, 1, 2, 0};

  for (int kt = 0; kt < KT; kt++) {
    asm volatile("cp.async.wait_group 1;\n");
    __syncthreads();
    const int st = kt & 1;
    const uint32_t stb = sbase + st * STAGE_BYTES;
#pragma unroll
    for (int kk = 0; kk < 2; kk++) {
      uint32_t areg[NP][4][4];
      uint32_t breg[NP][4][2];
#pragma unroll
      for (int p = 0; p < NP; p++) {
#pragma unroll
        for (int i = 0; i < 4; i++) {
          int row = wm * 64 + i * 16 + (lane & 15);
          int kb = kk * 32 + ((lane >> 4) << 4);
          uint32_t off = (uint32_t)(row * 64 + kb);
          off ^= (off >> 3) & 0x30;
          uint32_t ad = stb + p * PLANE_BYTES + off;
          asm volatile(
              "ldmatrix.sync.aligned.m8n8.x4.shared.b16 {%0,%1,%2,%3},[%4];"
              : "=r"(areg[p][i][0]), "=r"(areg[p][i][1]),
                "=r"(areg[p][i][2]), "=r"(areg[p][i][3])
              : "r"(ad));
        }
#pragma unroll
        for (int j = 0; j < 4; j++) {
          int row = wn * 32 + j * 8 + (lane & 7);
          int kb = kk * 32 + (((lane >> 3) & 1) << 4);
          uint32_t off = (uint32_t)(row * 64 + kb);
          off ^= (off >> 3) & 0x30;
          uint32_t ad = stb + (NP + p) * PLANE_BYTES + off;
          asm volatile(
              "ldmatrix.sync.aligned.m8n8.x2.shared.b16 {%0,%1},[%2];"
              : "=r"(breg[p][j][0]), "=r"(breg[p][j][1])
              : "r"(ad));
        }
      }
#pragma unroll
      for (int p = 0; p < NPROD; p++)
#pragma unroll
        for (int i = 0; i < 4; i++)
#pragma unroll
          for (int j = 0; j < 4; j++)
            mma16816(acc[i][j], areg[PAi[p]][i], breg[PBi[p]][j]);
    }
    __syncthreads();
    if (kt + 2 < KT) ISSUE_STAGE(kt + 2, st);
    asm volatile("cp.async.commit_group;\n");
  }
#undef ISSUE_STAGE

  // epilogue
#pragma unroll
  for (int i = 0; i < 4; i++) {
#pragma unroll
    for (int j = 0; j < 4; j++) {
      int n = n0 + wn * 32 + j * 8 + t * 2;
      int r0 = m0 + wm * 64 + i * 16 + g;
      float bn0 = __ldg(bias + n), bn1 = __ldg(bias + n + 1);
      float v[4];
      v[0] = acc[i][j][0] + bn0; v[1] = acc[i][j][1] + bn1;
      v[2] = acc[i][j][2] + bn0; v[3] = acc[i][j][3] + bn1;
      if (RELU) {
#pragma unroll
        for (int r = 0; r < 4; r++) v[r] = fmaxf(v[r], 0.0f);
      }
      if (NOUT == 0) {
        *(float2*)(Cf + (size_t)r0 * N + n) = make_float2(v[0], v[1]);
        *(float2*)(Cf + (size_t)(r0 + 8) * N + n) = make_float2(v[2], v[3]);
      } else {
#pragma unroll
        for (int half = 0; half < 2; half++) {
          size_t base = (size_t)(r0 + half * 8) * N + n;
          float x0 = v[half * 2], x1 = v[half * 2 + 1];
          __nv_bfloat16 a0 = __float2bfloat16_rn(x0);
          __nv_bfloat16 a1 = __float2bfloat16_rn(x1);
          float r0f = x0 - __bfloat162float(a0);
          float r1f = x1 - __bfloat162float(a1);
          __nv_bfloat16 c0 = __float2bfloat16_rn(r0f);
          __nv_bfloat16 c1 = __float2bfloat16_rn(r1f);
          *(__nv_bfloat162*)(O1 + base) = __nv_bfloat162(a0, a1);
          *(__nv_bfloat162*)(O2 + base) = __nv_bfloat162(c0, c1);
          if (NOUT == 3) {
            float s0 = r0f - __bfloat162float(c0);
            float s1 = r1f - __bfloat162float(c1);
            *(__nv_bfloat162*)(O3 + base) =
                __nv_bfloat162(__float2bfloat16_rn(s0), __float2bfloat16_rn(s1));
          }
        }
      }
    }
  }
}

// ---------------- SIMT SGEMM (only for K=32 z@W3) --------------------------
template<bool RELU>
__global__ void __launch_bounds__(256)
sgemm_nt(const float* __restrict__ A, const float* __restrict__ Bw,
         const float* __restrict__ bias, float* __restrict__ C,
         int M, int N, int K) {
  __shared__ float As[16][132];
  __shared__ float Bs[16][132];
  const int tid = threadIdx.x;
  const int tx = tid & 15, ty = tid >> 4;
  const int m0 = blockIdx.y << 7, n0 = blockIdx.x << 7;
  const float* Ab = A + (size_t)m0 * K;
  const float* Bb = Bw + (size_t)n0 * K;
  const int lrow = tid >> 2;
  const int seg  = tid & 3;
  float acc[8][8];
#pragma unroll
  for (int i = 0; i < 8; i++)
#pragma unroll
    for (int j = 0; j < 8; j++) acc[i][j] = 0.0f;

  for (int k0 = 0; k0 < K; k0 += 16) {
#pragma unroll
    for (int s = 0; s < 2; s++) {
      int r = lrow + s * 64;
      float4 av = *(const float4*)(Ab + (size_t)r * K + k0 + seg * 4);
      As[seg*4+0][r] = av.x; As[seg*4+1][r] = av.y;
      As[seg*4+2][r] = av.z; As[seg*4+3][r] = av.w;
      float4 bv = *(const float4*)(Bb + (size_t)r * K + k0 + seg * 4);
      Bs[seg*4+0][r] = bv.x; Bs[seg*4+1][r] = bv.y;
      Bs[seg*4+2][r] = bv.z; Bs[seg*4+3][r] = bv.w;
    }
    __syncthreads();
#pragma unroll
    for (int kk = 0; kk < 16; kk++) {
      float ar[8], br[8];
#pragma unroll
      for (int i = 0; i < 8; i++) ar[i] = As[kk][ty*8 + i];
#pragma unroll
      for (int j = 0; j < 8; j++) br[j] = Bs[kk][tx*8 + j];
#pragma unroll
      for (int i = 0; i < 8; i++)
#pragma unroll
        for (int j = 0; j < 8; j++)
          acc[i][j] += ar[i] * br[j];
    }
    __syncthreads();
  }
#pragma unroll
  for (int i = 0; i < 8; i++) {
    int m = m0 + ty*8 + i;
    float* crow = C + (size_t)m * N + n0 + tx*8;
#pragma unroll
    for (int j = 0; j < 8; j++) {
      float v = acc[i][j] + bias[n0 + tx*8 + j];
      if (RELU) v = fmaxf(v, 0.0f);
      crow[j] = v;
    }
  }
}

// ---------------- fused mu / kappa head ------------------------------------
__global__ void __launch_bounds__(128)
mukappa_kernel(const float* __restrict__ h2, const float* __restrict__ Wmu,
               const float* __restrict__ bmu, const float* __restrict__ Wk,
               const float* __restrict__ bk, float* __restrict__ mu_out,
               float* __restrict__ kap_out) {
  __shared__ float hs[HH];
  __shared__ float outv[33];
  const int r = blockIdx.x;
  const int tid = threadIdx.x;
  ((float4*)hs)[tid] = ((const float4*)(h2 + (size_t)r * HH))[tid];
  __syncthreads();
  const int w = tid >> 5, lane = tid & 31;
  for (int j = w; j < 33; j += 4) {
    const float* wr = (j < 32) ? (Wmu + (size_t)j * HH) : Wk;
    float s = 0.0f;
#pragma unroll 4
    for (int t = lane; t < HH; t += 32) s += hs[t] * wr[t];
#pragma unroll
    for (int off = 16; off; off >>= 1) s += __shfl_down_sync(0xffffffffu, s, off);
    if (lane == 0) outv[j] = s + ((j < 32) ? bmu[j] : bk[0]);
  }
  __syncthreads();
  if (tid < 32) {
    float m = outv[tid];
    float ss = m * m;
#pragma unroll
    for (int off = 16; off; off >>= 1) ss += __shfl_xor_sync(0xffffffffu, ss, off);
    float nf = sqrtf(ss) + 1e-8f;
    mu_out[(size_t)r * 32 + tid] = m / nf;
    if (tid == 0) {
      float xx = outv[32];
      float sp = fmaxf(xx, 0.0f) + log1pf(expf(-fabsf(xx)));
      kap_out[r] = sp + 1.0f;
    }
  }
}

// ---------------- vMF: Wood scan + tangent normals + Householder -----------
__global__ void __launch_bounds__(256)
vmf_z_kernel(const float* __restrict__ mu, const float* __restrict__ kap,
             const float* __restrict__ eps_arr, const float* __restrict__ u_arr,
             float* __restrict__ z) {
  int i = blockIdx.x * blockDim.x + threadIdx.x;
  if (i >= B_SZ) return;
  float k = kap[i];
  float sq = sqrtf(__fadd_rn(__fmul_rn(__fmul_rn(4.0f, k), k), 961.0f));
  float b  = __fdiv_rn(__fadd_rn(__fmul_rn(-2.0f, k), sq), 31.0f);
  float a  = __fdiv_rn(__fadd_rn(__fadd_rn(31.0f, __fmul_rn(2.0f, k)), sq), 4.0f);
  float d  = __fsub_rn(__fdiv_rn(__fmul_rn(__fmul_rn(4.0f, a), b), __fadd_rn(1.0f, b)),
                       __fmul_rn(31.0f, logf(31.0f)));
  float omb = __fsub_rn(1.0f, b), opb = __fadd_rn(1.0f, b);
  float ab2 = __fmul_rn(__fmul_rn(2.0f, a), b);
  float w = 0.0f; bool acc = false;
  for (int r = 0; r < NROUNDS; r++) {
    float eps = eps_arr[r * B_SZ + i];
    float u   = u_arr[r * B_SZ + i];
    float denom = __fsub_rn(1.0f, __fmul_rn(omb, eps));
    float wp = __fdiv_rn(__fsub_rn(1.0f, __fmul_rn(opb, eps)), denom);
    float t  = __fdiv_rn(ab2, denom);
    bool ok = __fadd_rn(__fsub_rn(__fmul_rn(31.0f, logf(t)), t), d)
              >= logf(__fadd_rn(u, 1e-20f));
    w = acc ? w : wp;
    acc = acc || ok;
  }
  w = fminf(fmaxf(w, -0.99999988f), 0.99999988f);

  uint2 kt = tf2x32(0u, 42u, 0u, 1u);
  float v[31]; float ss = 0.0f;
#pragma unroll
  for (int j = 0; j < 31; j++) {
    uint2 o = tf2x32(kt.x, kt.y, 0u, (uint32_t)(i * 31 + j));
    float xn = jax_normal_from_bits(o.x ^ o.y);
    v[j] = xn; ss += xn * xn;
  }
  float nf = sqrtf(ss) + 1e-12f;
  float s = sqrtf(__fsub_rn(1.0f, __fmul_rn(w, w)));

  const float* mrow = mu + (size_t)i * 32;
  float mloc[32];
#pragma unroll
  for (int c = 0; c < 32; c++) mloc[c] = mrow[c];
  float un2 = 0.0f;
#pragma unroll
  for (int c = 0; c < 32; c++) {
    float uh = ((c == 0) ? 1.0f : 0.0f) - mloc[c];
    un2 += uh * uh;
  }
  float unf = sqrtf(un2) + 1e-8f;
  float dot = 0.0f;
#pragma unroll
  for (int c = 0; c < 32; c++) {
    float ze = (c == 0) ? w : s * (v[c - 1] / nf);
    float uh = (((c == 0) ? 1.0f : 0.0f) - mloc[c]) / unf;
    dot += ze * uh;
  }
  float td = 2.0f * dot;
#pragma unroll
  for (int c = 0; c < 32; c++) {
    float ze = (c == 0) ? w : s * (v[c - 1] / nf);
    float uh = (((c == 0) ? 1.0f : 0.0f) - mloc[c]) / unf;
    z[(size_t)i * 32 + c] = ze - td * uh;
  }
}

// ---------------- launch ----------------------------------------------------
extern "C" void kernel_launch(void* const* d_in, const int* in_sizes, int n_in,
                              void* d_out, int out_size) {
  const float* x   = (const float*)d_in[0];
  const float* W1  = (const float*)d_in[1];
  const float* b1  = (const float*)d_in[2];
  const float* W2  = (const float*)d_in[3];
  const float* b2  = (const float*)d_in[4];
  const float* Wmu = (const float*)d_in[5];
  const float* bmu = (const float*)d_in[6];
  const float* Wk  = (const float*)d_in[7];
  const float* bk  = (const float*)d_in[8];
  const float* W3  = (const float*)d_in[9];
  const float* b3  = (const float*)d_in[10];
  const float* W4  = (const float*)d_in[11];
  const float* b4  = (const float*)d_in[12];
  const float* W5  = (const float*)d_in[13];
  const float* b5  = (const float*)d_in[14];

  float* out = (float*)d_out;
  float* x_recon = out;
  float* mu_out  = out + (size_t)B_SZ * D_SZ;
  float* kap_out = mu_out + (size_t)B_SZ * L_SZ;

  float *h2, *zbuf, *epsb, *ub;
  __nv_bfloat16 *xa, *h1p, *h3p, *h4p, *w1p, *w2p, *w4p, *w5p;
  cudaGetSymbolAddress((void**)&h2,   g_h2);
  cudaGetSymbolAddress((void**)&zbuf, g_z);
  cudaGetSymbolAddress((void**)&epsb, g_eps);
  cudaGetSymbolAddress((void**)&ub,   g_u);
  cudaGetSymbolAddress((void**)&xa,   g_xa);
  cudaGetSymbolAddress((void**)&h1p,  g_h1p);
  cudaGetSymbolAddress((void**)&h3p,  g_h3p);
  cudaGetSymbolAddress((void**)&h4p,  g_h4p);
  cudaGetSymbolAddress((void**)&w1p,  g_W1p);
  cudaGetSymbolAddress((void**)&w2p,  g_W2p);
  cudaGetSymbolAddress((void**)&w4p,  g_W4p);
  cudaGetSymbolAddress((void**)&w5p,  g_W5p);

  const size_t xaP  = (size_t)B_SZ * D_SZ;
  const size_t h1P  = (size_t)B_SZ * H_SZ;
  const size_t h3P  = (size_t)B_SZ * HH;
  const size_t h4P  = (size_t)B_SZ * H_SZ;
  const size_t w1P  = (size_t)H_SZ * D_SZ;
  const size_t w2P  = (size_t)HH * H_SZ;
  const size_t w4P  = (size_t)H_SZ * HH;
  const size_t w5P  = (size_t)D_SZ * H_SZ;

  // dynamic smem opt-in (idempotent)
  cudaFuncSetAttribute(mma_gemm<3,6,true,3>,  cudaFuncAttributeMaxDynamicSharedMemorySize, 98304);
  cudaFuncSetAttribute(mma_gemm<3,6,true,0>,  cudaFuncAttributeMaxDynamicSharedMemorySize, 98304);
  cudaFuncSetAttribute(mma_gemm<2,3,true,2>,  cudaFuncAttributeMaxDynamicSharedMemorySize, 65536);
  cudaFuncSetAttribute(mma_gemm<2,3,false,0>, cudaFuncAttributeMaxDynamicSharedMemorySize, 65536);

  // RNG (independent of everything)
  rng_kernel<<<(NROUNDS * B_SZ) / 256, 256>>>(epsb, ub);

  // splits of inputs/weights
  split_kernel<<<(unsigned)((xaP + 255) / 256), 256>>>(x,  xa,        xa + xaP,  xa + 2*xaP,  xaP);
  split_kernel<<<(unsigned)((w1P + 255) / 256), 256>>>(W1, w1p,       w1p + w1P, w1p + 2*w1P, w1P);
  split_kernel<<<(unsigned)((w2P + 255) / 256), 256>>>(W2, w2p,       w2p + w2P, w2p + 2*w2P, w2P);
  split_kernel<<<(unsigned)((w4P + 255) / 256), 256>>>(W4, w4p,       w4p + w4P, nullptr,     w4P);
  split_kernel<<<(unsigned)((w5P + 255) / 256), 256>>>(W5, w5p,       w5p + w5P, nullptr,     w5P);

  // encoder (bf16x6 ~ fp32 accuracy)
  mma_gemm<3,6,true,3><<<dim3(H_SZ/128, B_SZ/128), 256, 98304>>>(
      xa, xa + xaP, xa + 2*xaP, w1p, w1p + w1P, w1p + 2*w1P,
      b1, nullptr, h1p, h1p + h1P, h1p + 2*h1P, B_SZ, H_SZ, D_SZ);
  mma_gemm<3,6,true,0><<<dim3(HH/128, B_SZ/128), 256, 98304>>>(
      h1p, h1p + h1P, h1p + 2*h1P, w2p, w2p + w2P, w2p + 2*w2P,
      b2, h2, nullptr, nullptr, nullptr, B_SZ, HH, H_SZ);

  // heads
  mukappa_kernel<<<B_SZ, 128>>>(h2, Wmu, bmu, Wk, bk, mu_out, kap_out);

  // sampling
  vmf_z_kernel<<<B_SZ/256, 256>>>(mu_out, kap_out, epsb, ub, zbuf);

  // decoder: GEMM3 SIMT fp32 (K=32) into h2 (reused as h3), then split
  sgemm_nt<true><<<dim3(HH/128, B_SZ/128), 256>>>(zbuf, W3, b3, h2, B_SZ, HH, L_SZ);
  split_kernel<<<(unsigned)((h3P + 255) / 256), 256>>>(h2, h3p, h3p + h3P, nullptr, h3P);

  // decoder bf16x3
  mma_gemm<2,3,true,2><<<dim3(H_SZ/128, B_SZ/128), 256, 65536>>>(
      h3p, h3p + h3P, nullptr, w4p, w4p + w4P, nullptr,
      b4, nullptr, h4p, h4p + h4P, nullptr, B_SZ, H_SZ, HH);
  mma_gemm<2,3,false,0><<<dim3(D_SZ/128, B_SZ/128), 256, 65536>>>(
      h4p, h4p + h4P, nullptr, w5p, w5p + w5P, nullptr,
      b5, x_recon, nullptr, nullptr, nullptr, B_SZ, D_SZ, H_SZ);
}

// round 15
// speedup vs baseline: 1.8239x; 1.0010x over previous
#include <cuda_runtime.h>
#include <cuda_bf16.h>
#include <cstdint>
#include <cstddef>

#define B_SZ 16384
#define D_SZ 2048
#define H_SZ 1024
#define HH   512
#define L_SZ 32
#define NROUNDS 32

// ---------------- scratch (device globals; no allocation allowed) ----------
__device__ float g_h2[(size_t)B_SZ * HH];     // h2 fp32 (mukappa input)
__device__ float g_z [(size_t)B_SZ * L_SZ];
__device__ float g_eps[(size_t)NROUNDS * B_SZ];
__device__ float g_u [(size_t)NROUNDS * B_SZ];

// bf16 split planes (plane p at offset p*planeElems)
__device__ __nv_bfloat16 g_xa [3 * (size_t)B_SZ * D_SZ];
__device__ __nv_bfloat16 g_h1p[3 * (size_t)B_SZ * H_SZ];
__device__ __nv_bfloat16 g_h3p[2 * (size_t)B_SZ * HH];
__device__ __nv_bfloat16 g_h4p[2 * (size_t)B_SZ * H_SZ];
__device__ __nv_bfloat16 g_W1p[3 * (size_t)H_SZ * D_SZ];
__device__ __nv_bfloat16 g_W2p[3 * (size_t)HH * H_SZ];
__device__ __nv_bfloat16 g_W4p[2 * (size_t)H_SZ * HH];
__device__ __nv_bfloat16 g_W5p[2 * (size_t)D_SZ * H_SZ];

// ---------------- JAX threefry2x32 (partitionable semantics) ---------------
__device__ __forceinline__ uint2 tf2x32(uint32_t k0, uint32_t k1,
                                        uint32_t x0, uint32_t x1) {
  uint32_t ks2 = k0 ^ k1 ^ 0x1BD11BDAu;
#define TFR(r) { x0 += x1; x1 = (x1 << (r)) | (x1 >> (32 - (r))); x1 ^= x0; }
  x0 += k0; x1 += k1;
  TFR(13) TFR(15) TFR(26) TFR(6)
  x0 += k1;  x1 += ks2 + 1u;
  TFR(17) TFR(29) TFR(16) TFR(24)
  x0 += ks2; x1 += k0 + 2u;
  TFR(13) TFR(15) TFR(26) TFR(6)
  x0 += k0;  x1 += k1 + 3u;
  TFR(17) TFR(29) TFR(16) TFR(24)
  x0 += k1;  x1 += ks2 + 4u;
  TFR(13) TFR(15) TFR(26) TFR(6)
  x0 += ks2; x1 += k0 + 5u;
#undef TFR
  return make_uint2(x0, x1);
}

__device__ __forceinline__ float u01f(uint32_t bits) {
  return __uint_as_float((bits >> 9) | 0x3f800000u) - 1.0f;
}

__device__ __forceinline__ float xla_erfinv(float x) {
  float t = __fmul_rn(x, x);
  float w = -log1pf(-t);
  float p;
  if (w < 5.0f) {
    w = __fadd_rn(w, -2.5f);
    p = 2.81022636e-08f;
    p = __fadd_rn(3.43273939e-07f, __fmul_rn(p, w));
    p = __fadd_rn(-3.5233877e-06f, __fmul_rn(p, w));
    p = __fadd_rn(-4.39150654e-06f, __fmul_rn(p, w));
    p = __fadd_rn(0.00021858087f, __fmul_rn(p, w));
    p = __fadd_rn(-0.00125372503f, __fmul_rn(p, w));
    p = __fadd_rn(-0.00417768164f, __fmul_rn(p, w));
    p = __fadd_rn(0.246640727f, __fmul_rn(p, w));
    p = __fadd_rn(1.50140941f, __fmul_rn(p, w));
  } else {
    w = __fadd_rn(sqrtf(w), -3.0f);
    p = -0.000200214257f;
    p = __fadd_rn(0.000100950558f, __fmul_rn(p, w));
    p = __fadd_rn(0.00134934322f, __fmul_rn(p, w));
    p = __fadd_rn(-0.00367342844f, __fmul_rn(p, w));
    p = __fadd_rn(0.00573950773f, __fmul_rn(p, w));
    p = __fadd_rn(-0.0076224613f, __fmul_rn(p, w));
    p = __fadd_rn(0.00943887047f, __fmul_rn(p, w));
    p = __fadd_rn(1.00167406f, __fmul_rn(p, w));
    p = __fadd_rn(2.83297682f, __fmul_rn(p, w));
  }
  return __fmul_rn(p, x);
}

__device__ __forceinline__ float jax_normal_from_bits(uint32_t bits) {
  const float lo = -0.99999994f;
  float f = u01f(bits);
  float uu = __fadd_rn(__fmul_rn(f, 2.0f), lo);
  uu = fmaxf(lo, uu);
  return __fmul_rn(1.41421356f, xla_erfinv(uu));
}

__device__ float loggamma15p5(uint2 ekey) {
  const float d = __fadd_rn(15.5f, -0.33333334f);
  const float c = __fdiv_rn(0.33333334f, sqrtf(d));
  uint2 key = tf2x32(ekey.x, ekey.y, 0u, 0u);
  float V = 1.0f;
  for (int it = 0; it < 256; it++) {
    uint2 nk = tf2x32(key.x, key.y, 0u, 0u);
    uint2 xk = tf2x32(key.x, key.y, 0u, 1u);
    uint2 Uk = tf2x32(key.x, key.y, 0u, 2u);
    key = nk;
    float xn = 0.0f, v = -1.0f;
    uint2 kx = xk;
    for (int jt = 0; jt < 256; jt++) {
      uint2 nk2 = tf2x32(kx.x, kx.y, 0u, 0u);
      uint2 sub = tf2x32(kx.x, kx.y, 0u, 1u);
      kx = nk2;
      uint2 ob = tf2x32(sub.x, sub.y, 0u, 0u);
      xn = jax_normal_from_bits(ob.x ^ ob.y);
      v = __fadd_rn(1.0f, __fmul_rn(xn, c));
      if (!(v <= 0.0f)) break;
    }
    float X = __fmul_rn(xn, xn);
    V = __fmul_rn(__fmul_rn(v, v), v);
    uint2 ou = tf2x32(Uk.x, Uk.y, 0u, 0u);
    float U = u01f(ou.x ^ ou.y);
    bool c1 = U >= __fsub_rn(1.0f, __fmul_rn(0.0331f, __fmul_rn(X, X)));
    float rhs = __fadd_rn(__fmul_rn(X, 0.5f),
                          __fmul_rn(d, __fadd_rn(__fsub_rn(1.0f, V), logf(V))));
    bool c2 = logf(U) >= rhs;
    if (!(c1 && c2)) break;
  }
  return __fadd_rn(logf(d), logf(V));
}

__global__ void __launch_bounds__(256)
rng_kernel(float* __restrict__ eps_arr, float* __restrict__ u_arr) {
  int t = blockIdx.x * blockDim.x + threadIdx.x;
  if (t >= NROUNDS * B_SZ) return;
  int r = t >> 14, i = t & 16383;
  uint2 k_rounds = tf2x32(0u, 42u, 0u, 0u);
  uint2 rk = tf2x32(k_rounds.x, k_rounds.y, 0u, (uint32_t)r);
  uint2 k1 = tf2x32(rk.x, rk.y, 0u, 0u);
  uint2 k2 = tf2x32(rk.x, rk.y, 0u, 1u);
  uint2 key_a = tf2x32(k1.x, k1.y, 0u, 0u);
  uint2 key_b = tf2x32(k1.x, k1.y, 0u, 1u);
  uint2 ka = tf2x32(key_a.x, key_a.y, 0u, (uint32_t)i);
  uint2 kb = tf2x32(key_b.x, key_b.y, 0u, (uint32_t)i);
  float lga = loggamma15p5(ka);
  float lgb = loggamma15p5(kb);
  float mx = fmaxf(lga, lgb);
  float ga = expf(__fsub_rn(lga, mx));
  float gb = expf(__fsub_rn(lgb, mx));
  eps_arr[t] = __fdiv_rn(ga, __fadd_rn(ga, gb));
  uint2 ou = tf2x32(k2.x, k2.y, 0u, (uint32_t)i);
  u_arr[t] = u01f(ou.x ^ ou.y);
}

// ---------------- vectorized bf16 split (8 elems / thread) -----------------
template <int NOUT>
__global__ void __launch_bounds__(256)
split8_kernel(const float4* __restrict__ in, uint4* __restrict__ p1,
              uint4* __restrict__ p2, uint4* __restrict__ p3, size_t n8) {
  size_t i = (size_t)blockIdx.x * 256 + threadIdx.x;
  if (i >= n8) return;
  float4 a = in[i * 2], b = in[i * 2 + 1];
  float x[8] = {a.x, a.y, a.z, a.w, b.x, b.y, b.z, b.w};
  __align__(16) __nv_bfloat16 q1[8], q2[8], q3[8];
#pragma unroll
  for (int c = 0; c < 8; c++) {
    __nv_bfloat16 b1 = __float2bfloat16_rn(x[c]);
    float r1 = x[c] - __bfloat162float(b1);
    __nv_bfloat16 b2 = __float2bfloat16_rn(r1);
    q1[c] = b1; q2[c] = b2;
    if (NOUT == 3) q3[c] = __float2bfloat16_rn(r1 - __bfloat162float(b2));
  }
  p1[i] = *(uint4*)q1;
  p2[i] = *(uint4*)q2;
  if (NOUT == 3) p3[i] = *(uint4*)q3;
}

// ---------------- tensor-core split GEMM (mma.sync, sm_80+ path) -----------
// C[M,N] = act(sum_products A@B^T + bias). A planes [M,K], B planes [N,K].
// 128x128 CTA tile, 8 warps of 64x32, KC=32, 3-stage cp.async pipeline.
__device__ __forceinline__ void mma16816(float* d, const uint32_t* a,
                                         const uint32_t* b) {
  asm volatile(
      "mma.sync.aligned.m16n8k16.row.col.f32.bf16.bf16.f32 "
      "{%0,%1,%2,%3},{%4,%5,%6,%7},{%8,%9},{%0,%1,%2,%3};"
      : "+f"(d[0]), "+f"(d[1]), "+f"(d[2]), "+f"(d[3])
      : "r"(a[0]), "r"(a[1]), "r"(a[2]), "r"(a[3]), "r"(b[0]), "r"(b[1]));
}

template <int NP, int NPROD, bool RELU, int NOUT>
__global__ void __launch_bounds__(256, 1)
mma_gemm(const __nv_bfloat16* __restrict__ A1, const __nv_bfloat16* __restrict__ A2,
         const __nv_bfloat16* __restrict__ A3,
         const __nv_bfloat16* __restrict__ B1, const __nv_bfloat16* __restrict__ B2,
         const __nv_bfloat16* __restrict__ B3,
         const float* __restrict__ bias,
         float* __restrict__ Cf,
         __nv_bfloat16* __restrict__ O1, __nv_bfloat16* __restrict__ O2,
         __nv_bfloat16* __restrict__ O3,
         int M, int N, int K) {
  extern __shared__ char smem[];
  constexpr int PLANES = 2 * NP;
  constexpr int PLANE_BYTES = 128 * 64;               // 128 rows x 32 bf16
  constexpr int STAGE_BYTES = PLANES * PLANE_BYTES;
  const int tid = threadIdx.x;
  const int wid = tid >> 5, lane = tid & 31;
  const int wm = wid >> 2, wn = wid & 3;              // 2 x 4 warps
  const int g = lane >> 2, t = lane & 3;
  const int m0 = blockIdx.y << 7, n0 = blockIdx.x << 7;
  const __nv_bfloat16* Ap[3] = {A1, A2, A3};
  const __nv_bfloat16* Bp[3] = {B1, B2, B3};
  uint32_t sbase = (uint32_t)__cvta_generic_to_shared(smem);

  float acc[4][4][4];
#pragma unroll
  for (int i = 0; i < 4; i++)
#pragma unroll
    for (int j = 0; j < 4; j++)
#pragma unroll
      for (int r = 0; r < 4; r++) acc[i][j][r] = 0.0f;

  const int KT = K >> 5;

#define ISSUE_STAGE(KT_IDX, STAGE)                                            \
  {                                                                           \
    int k0_ = (KT_IDX) << 5;                                                  \
    _Pragma("unroll")                                                         \
    for (int pl = 0; pl < PLANES; pl++) {                                     \
      const __nv_bfloat16* bptr = (pl < NP) ? Ap[pl] : Bp[pl - NP];           \
      int roff = (pl < NP) ? m0 : n0;                                         \
      _Pragma("unroll")                                                       \
      for (int h = 0; h < 2; h++) {                                           \
        int c = tid + h * 256;                                                \
        int row = c >> 2, seg = c & 3;                                        \
        const __nv_bfloat16* src =                                            \
            bptr + (size_t)(roff + row) * K + k0_ + seg * 8;                  \
        uint32_t off = (uint32_t)(row * 64 + seg * 16);                       \
        off ^= (off >> 3) & 0x30;                                             \
        uint32_t dst = sbase + (STAGE) * STAGE_BYTES + pl * PLANE_BYTES + off;\
        asm volatile("cp.async.cg.shared.global [%0], [%1], 16;\n" ::         \
                         "r"(dst), "l"(src));                                 \
      }                                                                       \
    }                                                                         \
  }

  ISSUE_STAGE(0, 0);
  asm volatile("cp.async.commit_group;\n");
  ISSUE_STAGE(1, 1);
  asm volatile("cp.async.commit_group;\n");
  ISSUE_STAGE(2, 2);
  asm volatile("cp.async.commit_group;\n");

  constexpr int PAi[6] = {0, 0, 1, 1, 0, 2};
  constexpr int PBi[6] = {0, 1, 0, 1, 2, 0};

  for (int kt = 0; kt < KT; kt++) {
    asm volatile("cp.async.wait_group 2;\n");
    __syncthreads();
    const int st = kt % 3;
    const uint32_t stb = sbase + st * STAGE_BYTES;
#pragma unroll
    for (int kk = 0; kk < 2; kk++) {
      uint32_t areg[NP][4][4];
      uint32_t breg[NP][4][2];
#pragma unroll
      for (int p = 0; p < NP; p++) {
#pragma unroll
        for (int i = 0; i < 4; i++) {
          int row = wm * 64 + i * 16 + (lane & 15);
          int kb = kk * 32 + ((lane >> 4) << 4);
          uint32_t off = (uint32_t)(row * 64 + kb);
          off ^= (off >> 3) & 0x30;
          uint32_t ad = stb + p * PLANE_BYTES + off;
          asm volatile(
              "ldmatrix.sync.aligned.m8n8.x4.shared.b16 {%0,%1,%2,%3},[%4];"
              : "=r"(areg[p][i][0]), "=r"(areg[p][i][1]),
                "=r"(areg[p][i][2]), "=r"(areg[p][i][3])
              : "r"(ad));
        }
#pragma unroll
        for (int j = 0; j < 4; j++) {
          int row = wn * 32 + j * 8 + (lane & 7);
          int kb = kk * 32 + (((lane >> 3) & 1) << 4);
          uint32_t off = (uint32_t)(row * 64 + kb);
          off ^= (off >> 3) & 0x30;
          uint32_t ad = stb + (NP + p) * PLANE_BYTES + off;
          asm volatile(
              "ldmatrix.sync.aligned.m8n8.x2.shared.b16 {%0,%1},[%2];"
              : "=r"(breg[p][j][0]), "=r"(breg[p][j][1])
              : "r"(ad));
        }
      }
#pragma unroll
      for (int p = 0; p < NPROD; p++)
#pragma unroll
        for (int i = 0; i < 4; i++)
#pragma unroll
          for (int j = 0; j < 4; j++)
            mma16816(acc[i][j], areg[PAi[p]][i], breg[PBi[p]][j]);
    }
    __syncthreads();
    if (kt + 3 < KT) ISSUE_STAGE(kt + 3, st);
    asm volatile("cp.async.commit_group;\n");
  }
#undef ISSUE_STAGE

  // epilogue
#pragma unroll
  for (int i = 0; i < 4; i++) {
#pragma unroll
    for (int j = 0; j < 4; j++) {
      int n = n0 + wn * 32 + j * 8 + t * 2;
      int r0 = m0 + wm * 64 + i * 16 + g;
      float bn0 = __ldg(bias + n), bn1 = __ldg(bias + n + 1);
      float v[4];
      v[0] = acc[i][j][0] + bn0; v[1] = acc[i][j][1] + bn1;
      v[2] = acc[i][j][2] + bn0; v[3] = acc[i][j][3] + bn1;
      if (RELU) {
#pragma unroll
        for (int r = 0; r < 4; r++) v[r] = fmaxf(v[r], 0.0f);
      }
      if (NOUT == 0) {
        *(float2*)(Cf + (size_t)r0 * N + n) = make_float2(v[0], v[1]);
        *(float2*)(Cf + (size_t)(r0 + 8) * N + n) = make_float2(v[2], v[3]);
      } else {
#pragma unroll
        for (int half = 0; half < 2; half++) {
          size_t base = (size_t)(r0 + half * 8) * N + n;
          float x0 = v[half * 2], x1 = v[half * 2 + 1];
          __nv_bfloat16 a0 = __float2bfloat16_rn(x0);
          __nv_bfloat16 a1 = __float2bfloat16_rn(x1);
          float r0f = x0 - __bfloat162float(a0);
          float r1f = x1 - __bfloat162float(a1);
          __nv_bfloat16 c0 = __float2bfloat16_rn(r0f);
          __nv_bfloat16 c1 = __float2bfloat16_rn(r1f);
          *(__nv_bfloat162*)(O1 + base) = __nv_bfloat162(a0, a1);
          *(__nv_bfloat162*)(O2 + base) = __nv_bfloat162(c0, c1);
          if (NOUT == 3) {
            float s0 = r0f - __bfloat162float(c0);
            float s1 = r1f - __bfloat162float(c1);
            *(__nv_bfloat162*)(O3 + base) =
                __nv_bfloat162(__float2bfloat16_rn(s0), __float2bfloat16_rn(s1));
          }
        }
      }
    }
  }
}

// ---------------- SIMT SGEMM for K=32 (z@W3), split-bf16 epilogue ----------
template <bool RELU, bool SPLIT>
__global__ void __launch_bounds__(256)
sgemm_nt(const float* __restrict__ A, const float* __restrict__ Bw,
         const float* __restrict__ bias, float* __restrict__ C,
         __nv_bfloat16* __restrict__ O1, __nv_bfloat16* __restrict__ O2,
         int M, int N, int K) {
  __shared__ float As[16][132];
  __shared__ float Bs[16][132];
  const int tid = threadIdx.x;
  const int tx = tid & 15, ty = tid >> 4;
  const int m0 = blockIdx.y << 7, n0 = blockIdx.x << 7;
  const float* Ab = A + (size_t)m0 * K;
  const float* Bb = Bw + (size_t)n0 * K;
  const int lrow = tid >> 2;
  const int seg  = tid & 3;
  float acc[8][8];
#pragma unroll
  for (int i = 0; i < 8; i++)
#pragma unroll
    for (int j = 0; j < 8; j++) acc[i][j] = 0.0f;

  for (int k0 = 0; k0 < K; k0 += 16) {
#pragma unroll
    for (int s = 0; s < 2; s++) {
      int r = lrow + s * 64;
      float4 av = *(const float4*)(Ab + (size_t)r * K + k0 + seg * 4);
      As[seg*4+0][r] = av.x; As[seg*4+1][r] = av.y;
      As[seg*4+2][r] = av.z; As[seg*4+3][r] = av.w;
      float4 bv = *(const float4*)(Bb + (size_t)r * K + k0 + seg * 4);
      Bs[seg*4+0][r] = bv.x; Bs[seg*4+1][r] = bv.y;
      Bs[seg*4+2][r] = bv.z; Bs[seg*4+3][r] = bv.w;
    }
    __syncthreads();
#pragma unroll
    for (int kk = 0; kk < 16; kk++) {
      float ar[8], br[8];
#pragma unroll
      for (int i = 0; i < 8; i++) ar[i] = As[kk][ty*8 + i];
#pragma unroll
      for (int j = 0; j < 8; j++) br[j] = Bs[kk][tx*8 + j];
#pragma unroll
      for (int i = 0; i < 8; i++)
#pragma unroll
        for (int j = 0; j < 8; j++)
          acc[i][j] += ar[i] * br[j];
    }
    __syncthreads();
  }
#pragma unroll
  for (int i = 0; i < 8; i++) {
    int m = m0 + ty*8 + i;
    int n = n0 + tx*8;
    float v[8];
#pragma unroll
    for (int j = 0; j < 8; j++) {
      v[j] = acc[i][j] + bias[n + j];
      if (RELU) v[j] = fmaxf(v[j], 0.0f);
    }
    if (!SPLIT) {
      float* crow = C + (size_t)m * N + n;
#pragma unroll
      for (int j = 0; j < 8; j++) crow[j] = v[j];
    } else {
      __align__(16) __nv_bfloat16 q1[8], q2[8];
#pragma unroll
      for (int j = 0; j < 8; j++) {
        __nv_bfloat16 b1 = __float2bfloat16_rn(v[j]);
        float r1 = v[j] - __bfloat162float(b1);
        q1[j] = b1; q2[j] = __float2bfloat16_rn(r1);
      }
      size_t base = (size_t)m * N + n;
      *(uint4*)(O1 + base) = *(uint4*)q1;
      *(uint4*)(O2 + base) = *(uint4*)q2;
    }
  }
}

// ---------------- fused mu / kappa head (8 rows per block) ------------------
// Per-dot arithmetic (lane-stride-32 accumulation, shfl_down reduction,
// shfl_xor norm) is bit-identical to the previous single-row version.
__global__ void __launch_bounds__(256)
mukappa_kernel(const float* __restrict__ h2, const float* __restrict__ Wmu,
               const float* __restrict__ bmu, const float* __restrict__ Wk,
               const float* __restrict__ bk, float* __restrict__ mu_out,
               float* __restrict__ kap_out) {
  __shared__ float hs[8][HH];
  __shared__ float wrow[HH];
  __shared__ float outv[8][33];
  const int r0 = blockIdx.x * 8;
  const int tid = threadIdx.x;
  const int wid = tid >> 5, lane = tid & 31;
#pragma unroll
  for (int q = 0; q < 4; q++) {
    int idx = tid + q * 256;          // 0..1023
    int row = idx >> 7, c4 = idx & 127;
    ((float4*)hs[row])[c4] = ((const float4*)(h2 + (size_t)(r0 + row) * HH))[c4];
  }
  __syncthreads();
  for (int j = 0; j < 33; j++) {
    const float* wr = (j < 32) ? (Wmu + (size_t)j * HH) : Wk;
    if (tid < 128) ((float4*)wrow)[tid] = ((const float4*)wr)[tid];
    __syncthreads();
    float s = 0.0f;
#pragma unroll 4
    for (int t = lane; t < HH; t += 32) s += hs[wid][t] * wrow[t];
#pragma unroll
    for (int off = 16; off; off >>= 1) s += __shfl_down_sync(0xffffffffu, s, off);
    if (lane == 0) outv[wid][j] = s + ((j < 32) ? bmu[j] : bk[0]);
    __syncthreads();
  }
  {
    float m = outv[wid][lane];
    float ss = m * m;
#pragma unroll
    for (int off = 16; off; off >>= 1) ss += __shfl_xor_sync(0xffffffffu, ss, off);
    float nf = sqrtf(ss) + 1e-8f;
    mu_out[(size_t)(r0 + wid) * 32 + lane] = m / nf;
    if (lane == 0) {
      float xx = outv[wid][32];
      float sp = fmaxf(xx, 0.0f) + log1pf(expf(-fabsf(xx)));
      kap_out[r0 + wid] = sp + 1.0f;
    }
  }
}

// ---------------- vMF: Wood scan + tangent normals + Householder -----------
__global__ void __launch_bounds__(256)
vmf_z_kernel(const float* __restrict__ mu, const float* __restrict__ kap,
             const float* __restrict__ eps_arr, const float* __restrict__ u_arr,
             float* __restrict__ z) {
  int i = blockIdx.x * blockDim.x + threadIdx.x;
  if (i >= B_SZ) return;
  float k = kap[i];
  float sq = sqrtf(__fadd_rn(__fmul_rn(__fmul_rn(4.0f, k), k), 961.0f));
  float b  = __fdiv_rn(__fadd_rn(__fmul_rn(-2.0f, k), sq), 31.0f);
  float a  = __fdiv_rn(__fadd_rn(__fadd_rn(31.0f, __fmul_rn(2.0f, k)), sq), 4.0f);
  float d  = __fsub_rn(__fdiv_rn(__fmul_rn(__fmul_rn(4.0f, a), b), __fadd_rn(1.0f, b)),
                       __fmul_rn(31.0f, logf(31.0f)));
  float omb = __fsub_rn(1.0f, b), opb = __fadd_rn(1.0f, b);
  float ab2 = __fmul_rn(__fmul_rn(2.0f, a), b);
  float w = 0.0f; bool acc = false;
  for (int r = 0; r < NROUNDS; r++) {
    float eps = eps_arr[r * B_SZ + i];
    float u   = u_arr[r * B_SZ + i];
    float denom = __fsub_rn(1.0f, __fmul_rn(omb, eps));
    float wp = __fdiv_rn(__fsub_rn(1.0f, __fmul_rn(opb, eps)), denom);
    float t  = __fdiv_rn(ab2, denom);
    bool ok = __fadd_rn(__fsub_rn(__fmul_rn(31.0f, logf(t)), t), d)
              >= logf(__fadd_rn(u, 1e-20f));
    w = acc ? w : wp;
    acc = acc || ok;
  }
  w = fminf(fmaxf(w, -0.99999988f), 0.99999988f);

  uint2 kt = tf2x32(0u, 42u, 0u, 1u);
  float v[31]; float ss = 0.0f;
#pragma unroll
  for (int j = 0; j < 31; j++) {
    uint2 o = tf2x32(kt.x, kt.y, 0u, (uint32_t)(i * 31 + j));
    float xn = jax_normal_from_bits(o.x ^ o.y);
    v[j] = xn; ss += xn * xn;
  }
  float nf = sqrtf(ss) + 1e-12f;
  float s = sqrtf(__fsub_rn(1.0f, __fmul_rn(w, w)));

  const float* mrow = mu + (size_t)i * 32;
  float mloc[32];
#pragma unroll
  for (int c = 0; c < 32; c++) mloc[c] = mrow[c];
  float un2 = 0.0f;
#pragma unroll
  for (int c = 0; c < 32; c++) {
    float uh = ((c == 0) ? 1.0f : 0.0f) - mloc[c];
    un2 += uh * uh;
  }
  float unf = sqrtf(un2) + 1e-8f;
  float dot = 0.0f;
#pragma unroll
  for (int c = 0; c < 32; c++) {
    float ze = (c == 0) ? w : s * (v[c - 1] / nf);
    float uh = (((c == 0) ? 1.0f : 0.0f) - mloc[c]) / unf;
    dot += ze * uh;
  }
  float td = 2.0f * dot;
#pragma unroll
  for (int c = 0; c < 32; c++) {
    float ze = (c == 0) ? w : s * (v[c - 1] / nf);
    float uh = (((c == 0) ? 1.0f : 0.0f) - mloc[c]) / unf;
    z[(size_t)i * 32 + c] = ze - td * uh;
  }
}

// ---------------- launch ----------------------------------------------------
extern "C" void kernel_launch(void* const* d_in, const int* in_sizes, int n_in,
                              void* d_out, int out_size) {
  const float* x   = (const float*)d_in[0];
  const float* W1  = (const float*)d_in[1];
  const float* b1  = (const float*)d_in[2];
  const float* W2  = (const float*)d_in[3];
  const float* b2  = (const float*)d_in[4];
  const float* Wmu = (const float*)d_in[5];
  const float* bmu = (const float*)d_in[6];
  const float* Wk  = (const float*)d_in[7];
  const float* bk  = (const float*)d_in[8];
  const float* W3  = (const float*)d_in[9];
  const float* b3  = (const float*)d_in[10];
  const float* W4  = (const float*)d_in[11];
  const float* b4  = (const float*)d_in[12];
  const float* W5  = (const float*)d_in[13];
  const float* b5  = (const float*)d_in[14];

  float* out = (float*)d_out;
  float* x_recon = out;
  float* mu_out  = out + (size_t)B_SZ * D_SZ;
  float* kap_out = mu_out + (size_t)B_SZ * L_SZ;

  float *h2, *zbuf, *epsb, *ub;
  __nv_bfloat16 *xa, *h1p, *h3p, *h4p, *w1p, *w2p, *w4p, *w5p;
  cudaGetSymbolAddress((void**)&h2,   g_h2);
  cudaGetSymbolAddress((void**)&zbuf, g_z);
  cudaGetSymbolAddress((void**)&epsb, g_eps);
  cudaGetSymbolAddress((void**)&ub,   g_u);
  cudaGetSymbolAddress((void**)&xa,   g_xa);
  cudaGetSymbolAddress((void**)&h1p,  g_h1p);
  cudaGetSymbolAddress((void**)&h3p,  g_h3p);
  cudaGetSymbolAddress((void**)&h4p,  g_h4p);
  cudaGetSymbolAddress((void**)&w1p,  g_W1p);
  cudaGetSymbolAddress((void**)&w2p,  g_W2p);
  cudaGetSymbolAddress((void**)&w4p,  g_W4p);
  cudaGetSymbolAddress((void**)&w5p,  g_W5p);

  const size_t xaP = (size_t)B_SZ * D_SZ;
  const size_t h1P = (size_t)B_SZ * H_SZ;
  const size_t h3P = (size_t)B_SZ * HH;
  const size_t h4P = (size_t)B_SZ * H_SZ;
  const size_t w1P = (size_t)H_SZ * D_SZ;
  const size_t w2P = (size_t)HH * H_SZ;
  const size_t w4P = (size_t)H_SZ * HH;
  const size_t w5P = (size_t)D_SZ * H_SZ;

  // 3-stage pipeline smem: stages * planes * 8KB
  const int SMEM6 = 3 * 6 * 8192;   // 147456
  const int SMEM4 = 3 * 4 * 8192;   // 98304
  cudaFuncSetAttribute(mma_gemm<3,6,true,3>,  cudaFuncAttributeMaxDynamicSharedMemorySize, SMEM6);
  cudaFuncSetAttribute(mma_gemm<3,6,true,0>,  cudaFuncAttributeMaxDynamicSharedMemorySize, SMEM6);
  cudaFuncSetAttribute(mma_gemm<2,3,true,2>,  cudaFuncAttributeMaxDynamicSharedMemorySize, SMEM4);
  cudaFuncSetAttribute(mma_gemm<2,3,false,0>, cudaFuncAttributeMaxDynamicSharedMemorySize, SMEM4);

  // RNG (independent of everything)
  rng_kernel<<<(NROUNDS * B_SZ) / 256, 256>>>(epsb, ub);

  // vectorized splits of inputs / weights
  split8_kernel<3><<<(unsigned)(xaP / 8 / 256), 256>>>(
      (const float4*)x, (uint4*)xa, (uint4*)(xa + xaP), (uint4*)(xa + 2*xaP), xaP / 8);
  split8_kernel<3><<<(unsigned)(w1P / 8 / 256), 256>>>(
      (const float4*)W1, (uint4*)w1p, (uint4*)(w1p + w1P), (uint4*)(w1p + 2*w1P), w1P / 8);
  split8_kernel<3><<<(unsigned)(w2P / 8 / 256), 256>>>(
      (const float4*)W2, (uint4*)w2p, (uint4*)(w2p + w2P), (uint4*)(w2p + 2*w2P), w2P / 8);
  split8_kernel<2><<<(unsigned)(w4P / 8 / 256), 256>>>(
      (const float4*)W4, (uint4*)w4p, (uint4*)(w4p + w4P), nullptr, w4P / 8);
  split8_kernel<2><<<(unsigned)(w5P / 8 / 256), 256>>>(
      (const float4*)W5, (uint4*)w5p, (uint4*)(w5p + w5P), nullptr, w5P / 8);

  // encoder (bf16x6 ~ fp32 accuracy)
  mma_gemm<3,6,true,3><<<dim3(H_SZ/128, B_SZ/128), 256, SMEM6>>>(
      xa, xa + xaP, xa + 2*xaP, w1p, w1p + w1P, w1p + 2*w1P,
      b1, nullptr, h1p, h1p + h1P, h1p + 2*h1P, B_SZ, H_SZ, D_SZ);
  mma_gemm<3,6,true,0><<<dim3(HH/128, B_SZ/128), 256, SMEM6>>>(
      h1p, h1p + h1P, h1p + 2*h1P, w2p, w2p + w2P, w2p + 2*w2P,
      b2, h2, nullptr, nullptr, nullptr, B_SZ, HH, H_SZ);

  // heads (8 rows/block, weight row staged in smem; math bit-identical)
  mukappa_kernel<<<B_SZ / 8, 256>>>(h2, Wmu, bmu, Wk, bk, mu_out, kap_out);

  // sampling
  vmf_z_kernel<<<B_SZ/256, 256>>>(mu_out, kap_out, epsb, ub, zbuf);

  // decoder: GEMM3 SIMT fp32 (K=32) with fused bf16-split epilogue
  sgemm_nt<true, true><<<dim3(HH/128, B_SZ/128), 256>>>(
      zbuf, W3, b3, nullptr, h3p, h3p + h3P, B_SZ, HH, L_SZ);

  // decoder bf16x3
  mma_gemm<2,3,true,2><<<dim3(H_SZ/128, B_SZ/128), 256, SMEM4>>>(
      h3p, h3p + h3P, nullptr, w4p, w4p + w4P, nullptr,
      b4, nullptr, h4p, h4p + h4P, nullptr, B_SZ, H_SZ, HH);
  mma_gemm<2,3,false,0><<<dim3(D_SZ/128, B_SZ/128), 256, SMEM4>>>(
      h4p, h4p + h4P, nullptr, w5p, w5p + w5P, nullptr,
      b5, x_recon, nullptr, nullptr, nullptr, B_SZ, D_SZ, H_SZ);
}

// round 16
// speedup vs baseline: 2.8664x; 1.5716x over previous
#include <cuda_runtime.h>
#include <cuda_fp16.h>
#include <cstdint>
#include <cstddef>

#define B_SZ 16384
#define D_SZ 2048
#define H_SZ 1024
#define HH   512
#define L_SZ 32
#define NROUNDS 32

// ---------------- scratch (device globals; no allocation allowed) ----------
__device__ float g_h2[(size_t)B_SZ * HH];     // h2 fp32 (mukappa input)
__device__ float g_z [(size_t)B_SZ * L_SZ];
__device__ float g_eps[(size_t)NROUNDS * B_SZ];
__device__ float g_u [(size_t)NROUNDS * B_SZ];

// fp16 split planes (plane p at offset p*planeElems)
__device__ __half g_xa [2 * (size_t)B_SZ * D_SZ];
__device__ __half g_h1p[2 * (size_t)B_SZ * H_SZ];
__device__ __half g_h3p[2 * (size_t)B_SZ * HH];
__device__ __half g_h4p[2 * (size_t)B_SZ * H_SZ];
__device__ __half g_W1p[2 * (size_t)H_SZ * D_SZ];
__device__ __half g_W2p[2 * (size_t)HH * H_SZ];
__device__ __half g_W4p[2 * (size_t)H_SZ * HH];
__device__ __half g_W5p[2 * (size_t)D_SZ * H_SZ];

// ---------------- JAX threefry2x32 (partitionable semantics) ---------------
__device__ __forceinline__ uint2 tf2x32(uint32_t k0, uint32_t k1,
                                        uint32_t x0, uint32_t x1) {
  uint32_t ks2 = k0 ^ k1 ^ 0x1BD11BDAu;
#define TFR(r) { x0 += x1; x1 = (x1 << (r)) | (x1 >> (32 - (r))); x1 ^= x0; }
  x0 += k0; x1 += k1;
  TFR(13) TFR(15) TFR(26) TFR(6)
  x0 += k1;  x1 += ks2 + 1u;
  TFR(17) TFR(29) TFR(16) TFR(24)
  x0 += ks2; x1 += k0 + 2u;
  TFR(13) TFR(15) TFR(26) TFR(6)
  x0 += k0;  x1 += k1 + 3u;
  TFR(17) TFR(29) TFR(16) TFR(24)
  x0 += k1;  x1 += ks2 + 4u;
  TFR(13) TFR(15) TFR(26) TFR(6)
  x0 += ks2; x1 += k0 + 5u;
#undef TFR
  return make_uint2(x0, x1);
}

__device__ __forceinline__ float u01f(uint32_t bits) {
  return __uint_as_float((bits >> 9) | 0x3f800000u) - 1.0f;
}

__device__ __forceinline__ float xla_erfinv(float x) {
  float t = __fmul_rn(x, x);
  float w = -log1pf(-t);
  float p;
  if (w < 5.0f) {
    w = __fadd_rn(w, -2.5f);
    p = 2.81022636e-08f;
    p = __fadd_rn(3.43273939e-07f, __fmul_rn(p, w));
    p = __fadd_rn(-3.5233877e-06f, __fmul_rn(p, w));
    p = __fadd_rn(-4.39150654e-06f, __fmul_rn(p, w));
    p = __fadd_rn(0.00021858087f, __fmul_rn(p, w));
    p = __fadd_rn(-0.00125372503f, __fmul_rn(p, w));
    p = __fadd_rn(-0.00417768164f, __fmul_rn(p, w));
    p = __fadd_rn(0.246640727f, __fmul_rn(p, w));
    p = __fadd_rn(1.50140941f, __fmul_rn(p, w));
  } else {
    w = __fadd_rn(sqrtf(w), -3.0f);
    p = -0.000200214257f;
    p = __fadd_rn(0.000100950558f, __fmul_rn(p, w));
    p = __fadd_rn(0.00134934322f, __fmul_rn(p, w));
    p = __fadd_rn(-0.00367342844f, __fmul_rn(p, w));
    p = __fadd_rn(0.00573950773f, __fmul_rn(p, w));
    p = __fadd_rn(-0.0076224613f, __fmul_rn(p, w));
    p = __fadd_rn(0.00943887047f, __fmul_rn(p, w));
    p = __fadd_rn(1.00167406f, __fmul_rn(p, w));
    p = __fadd_rn(2.83297682f, __fmul_rn(p, w));
  }
  return __fmul_rn(p, x);
}

__device__ __forceinline__ float jax_normal_from_bits(uint32_t bits) {
  const float lo = -0.99999994f;
  float f = u01f(bits);
  float uu = __fadd_rn(__fmul_rn(f, 2.0f), lo);
  uu = fmaxf(lo, uu);
  return __fmul_rn(1.41421356f, xla_erfinv(uu));
}

__device__ float loggamma15p5(uint2 ekey) {
  const float d = __fadd_rn(15.5f, -0.33333334f);
  const float c = __fdiv_rn(0.33333334f, sqrtf(d));
  uint2 key = tf2x32(ekey.x, ekey.y, 0u, 0u);
  float V = 1.0f;
  for (int it = 0; it < 256; it++) {
    uint2 nk = tf2x32(key.x, key.y, 0u, 0u);
    uint2 xk = tf2x32(key.x, key.y, 0u, 1u);
    uint2 Uk = tf2x32(key.x, key.y, 0u, 2u);
    key = nk;
    float xn = 0.0f, v = -1.0f;
    uint2 kx = xk;
    for (int jt = 0; jt < 256; jt++) {
      uint2 nk2 = tf2x32(kx.x, kx.y, 0u, 0u);
      uint2 sub = tf2x32(kx.x, kx.y, 0u, 1u);
      kx = nk2;
      uint2 ob = tf2x32(sub.x, sub.y, 0u, 0u);
      xn = jax_normal_from_bits(ob.x ^ ob.y);
      v = __fadd_rn(1.0f, __fmul_rn(xn, c));
      if (!(v <= 0.0f)) break;
    }
    float X = __fmul_rn(xn, xn);
    V = __fmul_rn(__fmul_rn(v, v), v);
    uint2 ou = tf2x32(Uk.x, Uk.y, 0u, 0u);
    float U = u01f(ou.x ^ ou.y);
    bool c1 = U >= __fsub_rn(1.0f, __fmul_rn(0.0331f, __fmul_rn(X, X)));
    float rhs = __fadd_rn(__fmul_rn(X, 0.5f),
                          __fmul_rn(d, __fadd_rn(__fsub_rn(1.0f, V), logf(V))));
    bool c2 = logf(U) >= rhs;
    if (!(c1 && c2)) break;
  }
  return __fadd_rn(logf(d), logf(V));
}

__global__ void __launch_bounds__(256)
rng_kernel(float* __restrict__ eps_arr, float* __restrict__ u_arr) {
  int t = blockIdx.x * blockDim.x + threadIdx.x;
  if (t >= NROUNDS * B_SZ) return;
  int r = t >> 14, i = t & 16383;
  uint2 k_rounds = tf2x32(0u, 42u, 0u, 0u);
  uint2 rk = tf2x32(k_rounds.x, k_rounds.y, 0u, (uint32_t)r);
  uint2 k1 = tf2x32(rk.x, rk.y, 0u, 0u);
  uint2 k2 = tf2x32(rk.x, rk.y, 0u, 1u);
  uint2 key_a = tf2x32(k1.x, k1.y, 0u, 0u);
  uint2 key_b = tf2x32(k1.x, k1.y, 0u, 1u);
  uint2 ka = tf2x32(key_a.x, key_a.y, 0u, (uint32_t)i);
  uint2 kb = tf2x32(key_b.x, key_b.y, 0u, (uint32_t)i);
  float lga = loggamma15p5(ka);
  float lgb = loggamma15p5(kb);
  float mx = fmaxf(lga, lgb);
  float ga = expf(__fsub_rn(lga, mx));
  float gb = expf(__fsub_rn(lgb, mx));
  eps_arr[t] = __fdiv_rn(ga, __fadd_rn(ga, gb));
  uint2 ou = tf2x32(k2.x, k2.y, 0u, (uint32_t)i);
  u_arr[t] = u01f(ou.x ^ ou.y);
}

// ---------------- vectorized fp16 split (8 elems / thread) -----------------
__global__ void __launch_bounds__(256)
split8_kernel(const float4* __restrict__ in, uint4* __restrict__ p1,
              uint4* __restrict__ p2, size_t n8) {
  size_t i = (size_t)blockIdx.x * 256 + threadIdx.x;
  if (i >= n8) return;
  float4 a = in[i * 2], b = in[i * 2 + 1];
  float x[8] = {a.x, a.y, a.z, a.w, b.x, b.y, b.z, b.w};
  __align__(16) __half q1[8], q2[8];
#pragma unroll
  for (int c = 0; c < 8; c++) {
    __half h1 = __float2half_rn(x[c]);
    float r1 = x[c] - __half2float(h1);
    q1[c] = h1; q2[c] = __float2half_rn(r1);
  }
  p1[i] = *(uint4*)q1;
  p2[i] = *(uint4*)q2;
}

// ---------------- tensor-core fp16 split GEMM (mma.sync) -------------------
// C[M,N] = act(sum_products A@B^T + bias). A,B each 2 fp16 planes [.,K].
// 128x128 CTA tile, 8 warps of 64x32, KC=32, 2-stage cp.async pipeline.
__device__ __forceinline__ void mma16816(float* d, const uint32_t* a,
                                         const uint32_t* b) {
  asm volatile(
      "mma.sync.aligned.m16n8k16.row.col.f32.f16.f16.f32 "
      "{%0,%1,%2,%3},{%4,%5,%6,%7},{%8,%9},{%0,%1,%2,%3};"
      : "+f"(d[0]), "+f"(d[1]), "+f"(d[2]), "+f"(d[3])
      : "r"(a[0]), "r"(a[1]), "r"(a[2]), "r"(a[3]), "r"(b[0]), "r"(b[1]));
}

template <int NPROD, bool RELU, int NOUT>
__global__ void __launch_bounds__(256, 1)
mma_gemm(const __half* __restrict__ A1, const __half* __restrict__ A2,
         const __half* __restrict__ B1, const __half* __restrict__ B2,
         const float* __restrict__ bias,
         float* __restrict__ Cf,
         __half* __restrict__ O1, __half* __restrict__ O2,
         int M, int N, int K) {
  extern __shared__ char smem[];
  constexpr int PLANES = 4;
  constexpr int PLANE_BYTES = 128 * 64;               // 128 rows x 32 fp16
  constexpr int STAGE_BYTES = PLANES * PLANE_BYTES;
  const int tid = threadIdx.x;
  const int wid = tid >> 5, lane = tid & 31;
  const int wm = wid >> 2, wn = wid & 3;              // 2 x 4 warps
  const int g = lane >> 2, t = lane & 3;
  const int m0 = blockIdx.y << 7, n0 = blockIdx.x << 7;
  const __half* Ap[2] = {A1, A2};
  const __half* Bp[2] = {B1, B2};
  uint32_t sbase = (uint32_t)__cvta_generic_to_shared(smem);

  float acc[4][4][4];
#pragma unroll
  for (int i = 0; i < 4; i++)
#pragma unroll
    for (int j = 0; j < 4; j++)
#pragma unroll
      for (int r = 0; r < 4; r++) acc[i][j][r] = 0.0f;

  const int KT = K >> 5;

#define ISSUE_STAGE(KT_IDX, STAGE)                                            \
  {                                                                           \
    int k0_ = (KT_IDX) << 5;                                                  \
    _Pragma("unroll")                                                         \
    for (int pl = 0; pl < PLANES; pl++) {                                     \
      const __half* bptr = (pl < 2) ? Ap[pl] : Bp[pl - 2];                    \
      int roff = (pl < 2) ? m0 : n0;                                          \
      _Pragma("unroll")                                                       \
      for (int h = 0; h < 2; h++) {                                           \
        int c = tid + h * 256;                                                \
        int row = c >> 2, seg = c & 3;                                        \
        const __half* src =                                                   \
            bptr + (size_t)(roff + row) * K + k0_ + seg * 8;                  \
        uint32_t off = (uint32_t)(row * 64 + seg * 16);                       \
        off ^= (off >> 3) & 0x30;                                             \
        uint32_t dst = sbase + (STAGE) * STAGE_BYTES + pl * PLANE_BYTES + off;\
        asm volatile("cp.async.cg.shared.global [%0], [%1], 16;\n" ::         \
                         "r"(dst), "l"(src));                                 \
      }                                                                       \
    }                                                                         \
  }

  ISSUE_STAGE(0, 0);
  asm volatile("cp.async.commit_group;\n");
  if (KT > 1) ISSUE_STAGE(1, 1);
  asm volatile("cp.async.commit_group;\n");

  // products: NPROD=3 -> A1B1, A1B2, A2B1 (error ~2^-24, fp32-equivalent)
  //           NPROD=2 -> A1B1, A1B2      (error ~2^-12 relative)
  constexpr int PAi[3] = {0, 0, 1};
  constexpr int PBi[3] = {0, 1, 0};

  for (int kt = 0; kt < KT; kt++) {
    asm volatile("cp.async.wait_group 1;\n");
    __syncthreads();
    const int st = kt & 1;
    const uint32_t stb = sbase + st * STAGE_BYTES;
#pragma unroll
    for (int kk = 0; kk < 2; kk++) {
      uint32_t areg[2][4][4];
      uint32_t breg[2][4][2];
#pragma unroll
      for (int p = 0; p < 2; p++) {
#pragma unroll
        for (int i = 0; i < 4; i++) {
          int row = wm * 64 + i * 16 + (lane & 15);
          int kb = kk * 32 + ((lane >> 4) << 4);
          uint32_t off = (uint32_t)(row * 64 + kb);
          off ^= (off >> 3) & 0x30;
          uint32_t ad = stb + p * PLANE_BYTES + off;
          asm volatile(
              "ldmatrix.sync.aligned.m8n8.x4.shared.b16 {%0,%1,%2,%3},[%4];"
              : "=r"(areg[p][i][0]), "=r"(areg[p][i][1]),
                "=r"(areg[p][i][2]), "=r"(areg[p][i][3])
              : "r"(ad));
        }
#pragma unroll
        for (int j = 0; j < 4; j++) {
          int row = wn * 32 + j * 8 + (lane & 7);
          int kb = kk * 32 + (((lane >> 3) & 1) << 4);
          uint32_t off = (uint32_t)(row * 64 + kb);
          off ^= (off >> 3) & 0x30;
          uint32_t ad = stb + (2 + p) * PLANE_BYTES + off;
          asm volatile(
              "ldmatrix.sync.aligned.m8n8.x2.shared.b16 {%0,%1},[%2];"
              : "=r"(breg[p][j][0]), "=r"(breg[p][j][1])
              : "r"(ad));
        }
      }
#pragma unroll
      for (int p = 0; p < NPROD; p++)
#pragma unroll
        for (int i = 0; i < 4; i++)
#pragma unroll
          for (int j = 0; j < 4; j++)
            mma16816(acc[i][j], areg[PAi[p]][i], breg[PBi[p]][j]);
    }
    __syncthreads();
    if (kt + 2 < KT) ISSUE_STAGE(kt + 2, st);
    asm volatile("cp.async.commit_group;\n");
  }
#undef ISSUE_STAGE

  // epilogue
#pragma unroll
  for (int i = 0; i < 4; i++) {
#pragma unroll
    for (int j = 0; j < 4; j++) {
      int n = n0 + wn * 32 + j * 8 + t * 2;
      int r0 = m0 + wm * 64 + i * 16 + g;
      float bn0 = __ldg(bias + n), bn1 = __ldg(bias + n + 1);
      float v[4];
      v[0] = acc[i][j][0] + bn0; v[1] = acc[i][j][1] + bn1;
      v[2] = acc[i][j][2] + bn0; v[3] = acc[i][j][3] + bn1;
      if (RELU) {
#pragma unroll
        for (int r = 0; r < 4; r++) v[r] = fmaxf(v[r], 0.0f);
      }
      if (NOUT == 0) {
        *(float2*)(Cf + (size_t)r0 * N + n) = make_float2(v[0], v[1]);
        *(float2*)(Cf + (size_t)(r0 + 8) * N + n) = make_float2(v[2], v[3]);
      } else {
#pragma unroll
        for (int half = 0; half < 2; half++) {
          size_t base = (size_t)(r0 + half * 8) * N + n;
          float x0 = v[half * 2], x1 = v[half * 2 + 1];
          __half a0 = __float2half_rn(x0);
          __half a1 = __float2half_rn(x1);
          __half c0 = __float2half_rn(x0 - __half2float(a0));
          __half c1 = __float2half_rn(x1 - __half2float(a1));
          *(__half2*)(O1 + base) = __half2(a0, a1);
          *(__half2*)(O2 + base) = __half2(c0, c1);
        }
      }
    }
  }
}

// ---------------- SIMT SGEMM for K=32 (z@W3), fp16-split epilogue ----------
__global__ void __launch_bounds__(256)
sgemm_nt_split(const float* __restrict__ A, const float* __restrict__ Bw,
               const float* __restrict__ bias,
               __half* __restrict__ O1, __half* __restrict__ O2,
               int M, int N, int K) {
  __shared__ float As[16][132];
  __shared__ float Bs[16][132];
  const int tid = threadIdx.x;
  const int tx = tid & 15, ty = tid >> 4;
  const int m0 = blockIdx.y << 7, n0 = blockIdx.x << 7;
  const float* Ab = A + (size_t)m0 * K;
  const float* Bb = Bw + (size_t)n0 * K;
  const int lrow = tid >> 2;
  const int seg  = tid & 3;
  float acc[8][8];
#pragma unroll
  for (int i = 0; i < 8; i++)
#pragma unroll
    for (int j = 0; j < 8; j++) acc[i][j] = 0.0f;

  for (int k0 = 0; k0 < K; k0 += 16) {
#pragma unroll
    for (int s = 0; s < 2; s++) {
      int r = lrow + s * 64;
      float4 av = *(const float4*)(Ab + (size_t)r * K + k0 + seg * 4);
      As[seg*4+0][r] = av.x; As[seg*4+1][r] = av.y;
      As[seg*4+2][r] = av.z; As[seg*4+3][r] = av.w;
      float4 bv = *(const float4*)(Bb + (size_t)r * K + k0 + seg * 4);
      Bs[seg*4+0][r] = bv.x; Bs[seg*4+1][r] = bv.y;
      Bs[seg*4+2][r] = bv.z; Bs[seg*4+3][r] = bv.w;
    }
    __syncthreads();
#pragma unroll
    for (int kk = 0; kk < 16; kk++) {
      float ar[8], br[8];
#pragma unroll
      for (int i = 0; i < 8; i++) ar[i] = As[kk][ty*8 + i];
#pragma unroll
      for (int j = 0; j < 8; j++) br[j] = Bs[kk][tx*8 + j];
#pragma unroll
      for (int i = 0; i < 8; i++)
#pragma unroll
        for (int j = 0; j < 8; j++)
          acc[i][j] += ar[i] * br[j];
    }
    __syncthreads();
  }
#pragma unroll
  for (int i = 0; i < 8; i++) {
    int m = m0 + ty*8 + i;
    int n = n0 + tx*8;
    __align__(16) __half q1[8], q2[8];
#pragma unroll
    for (int j = 0; j < 8; j++) {
      float v = fmaxf(acc[i][j] + bias[n + j], 0.0f);
      __half h1 = __float2half_rn(v);
      q1[j] = h1; q2[j] = __float2half_rn(v - __half2float(h1));
    }
    size_t base = (size_t)m * N + n;
    *(uint4*)(O1 + base) = *(uint4*)q1;
    *(uint4*)(O2 + base) = *(uint4*)q2;
  }
}

// ---------------- fused mu / kappa head (8 rows per block) ------------------
__global__ void __launch_bounds__(256)
mukappa_kernel(const float* __restrict__ h2, const float* __restrict__ Wmu,
               const float* __restrict__ bmu, const float* __restrict__ Wk,
               const float* __restrict__ bk, float* __restrict__ mu_out,
               float* __restrict__ kap_out) {
  __shared__ float hs[8][HH];
  __shared__ float wrow[HH];
  __shared__ float outv[8][33];
  const int r0 = blockIdx.x * 8;
  const int tid = threadIdx.x;
  const int wid = tid >> 5, lane = tid & 31;
#pragma unroll
  for (int q = 0; q < 4; q++) {
    int idx = tid + q * 256;
    int row = idx >> 7, c4 = idx & 127;
    ((float4*)hs[row])[c4] = ((const float4*)(h2 + (size_t)(r0 + row) * HH))[c4];
  }
  __syncthreads();
  for (int j = 0; j < 33; j++) {
    const float* wr = (j < 32) ? (Wmu + (size_t)j * HH) : Wk;
    if (tid < 128) ((float4*)wrow)[tid] = ((const float4*)wr)[tid];
    __syncthreads();
    float s = 0.0f;
#pragma unroll 4
    for (int t = lane; t < HH; t += 32) s += hs[wid][t] * wrow[t];
#pragma unroll
    for (int off = 16; off; off >>= 1) s += __shfl_down_sync(0xffffffffu, s, off);
    if (lane == 0) outv[wid][j] = s + ((j < 32) ? bmu[j] : bk[0]);
    __syncthreads();
  }
  {
    float m = outv[wid][lane];
    float ss = m * m;
#pragma unroll
    for (int off = 16; off; off >>= 1) ss += __shfl_xor_sync(0xffffffffu, ss, off);
    float nf = sqrtf(ss) + 1e-8f;
    mu_out[(size_t)(r0 + wid) * 32 + lane] = m / nf;
    if (lane == 0) {
      float xx = outv[wid][32];
      float sp = fmaxf(xx, 0.0f) + log1pf(expf(-fabsf(xx)));
      kap_out[r0 + wid] = sp + 1.0f;
    }
  }
}

// ---------------- vMF: Wood scan + tangent normals + Householder -----------
__global__ void __launch_bounds__(256)
vmf_z_kernel(const float* __restrict__ mu, const float* __restrict__ kap,
             const float* __restrict__ eps_arr, const float* __restrict__ u_arr,
             float* __restrict__ z) {
  int i = blockIdx.x * blockDim.x + threadIdx.x;
  if (i >= B_SZ) return;
  float k = kap[i];
  float sq = sqrtf(__fadd_rn(__fmul_rn(__fmul_rn(4.0f, k), k), 961.0f));
  float b  = __fdiv_rn(__fadd_rn(__fmul_rn(-2.0f, k), sq), 31.0f);
  float a  = __fdiv_rn(__fadd_rn(__fadd_rn(31.0f, __fmul_rn(2.0f, k)), sq), 4.0f);
  float d  = __fsub_rn(__fdiv_rn(__fmul_rn(__fmul_rn(4.0f, a), b), __fadd_rn(1.0f, b)),
                       __fmul_rn(31.0f, logf(31.0f)));
  float omb = __fsub_rn(1.0f, b), opb = __fadd_rn(1.0f, b);
  float ab2 = __fmul_rn(__fmul_rn(2.0f, a), b);
  float w = 0.0f; bool acc = false;
  for (int r = 0; r < NROUNDS; r++) {
    float eps = eps_arr[r * B_SZ + i];
    float u   = u_arr[r * B_SZ + i];
    float denom = __fsub_rn(1.0f, __fmul_rn(omb, eps));
    float wp = __fdiv_rn(__fsub_rn(1.0f, __fmul_rn(opb, eps)), denom);
    float t  = __fdiv_rn(ab2, denom);
    bool ok = __fadd_rn(__fsub_rn(__fmul_rn(31.0f, logf(t)), t), d)
              >= logf(__fadd_rn(u, 1e-20f));
    w = acc ? w : wp;
    acc = acc || ok;
  }
  w = fminf(fmaxf(w, -0.99999988f), 0.99999988f);

  uint2 kt = tf2x32(0u, 42u, 0u, 1u);
  float v[31]; float ss = 0.0f;
#pragma unroll
  for (int j = 0; j < 31; j++) {
    uint2 o = tf2x32(kt.x, kt.y, 0u, (uint32_t)(i * 31 + j));
    float xn = jax_normal_from_bits(o.x ^ o.y);
    v[j] = xn; ss += xn * xn;
  }
  float nf = sqrtf(ss) + 1e-12f;
  float s = sqrtf(__fsub_rn(1.0f, __fmul_rn(w, w)));

  const float* mrow = mu + (size_t)i * 32;
  float mloc[32];
#pragma unroll
  for (int c = 0; c < 32; c++) mloc[c] = mrow[c];
  float un2 = 0.0f;
#pragma unroll
  for (int c = 0; c < 32; c++) {
    float uh = ((c == 0) ? 1.0f : 0.0f) - mloc[c];
    un2 += uh * uh;
  }
  float unf = sqrtf(un2) + 1e-8f;
  float dot = 0.0f;
#pragma unroll
  for (int c = 0; c < 32; c++) {
    float ze = (c == 0) ? w : s * (v[c - 1] / nf);
    float uh = (((c == 0) ? 1.0f : 0.0f) - mloc[c]) / unf;
    dot += ze * uh;
  }
  float td = 2.0f * dot;
#pragma unroll
  for (int c = 0; c < 32; c++) {
    float ze = (c == 0) ? w : s * (v[c - 1] / nf);
    float uh = (((c == 0) ? 1.0f : 0.0f) - mloc[c]) / unf;
    z[(size_t)i * 32 + c] = ze - td * uh;
  }
}

// ---------------- launch ----------------------------------------------------
extern "C" void kernel_launch(void* const* d_in, const int* in_sizes, int n_in,
                              void* d_out, int out_size) {
  const float* x   = (const float*)d_in[0];
  const float* W1  = (const float*)d_in[1];
  const float* b1  = (const float*)d_in[2];
  const float* W2  = (const float*)d_in[3];
  const float* b2  = (const float*)d_in[4];
  const float* Wmu = (const float*)d_in[5];
  const float* bmu = (const float*)d_in[6];
  const float* Wk  = (const float*)d_in[7];
  const float* bk  = (const float*)d_in[8];
  const float* W3  = (const float*)d_in[9];
  const float* b3  = (const float*)d_in[10];
  const float* W4  = (const float*)d_in[11];
  const float* b4  = (const float*)d_in[12];
  const float* W5  = (const float*)d_in[13];
  const float* b5  = (const float*)d_in[14];

  float* out = (float*)d_out;
  float* x_recon = out;
  float* mu_out  = out + (size_t)B_SZ * D_SZ;
  float* kap_out = mu_out + (size_t)B_SZ * L_SZ;

  float *h2, *zbuf, *epsb, *ub;
  __half *xa, *h1p, *h3p, *h4p, *w1p, *w2p, *w4p, *w5p;
  cudaGetSymbolAddress((void**)&h2,   g_h2);
  cudaGetSymbolAddress((void**)&zbuf, g_z);
  cudaGetSymbolAddress((void**)&epsb, g_eps);
  cudaGetSymbolAddress((void**)&ub,   g_u);
  cudaGetSymbolAddress((void**)&xa,   g_xa);
  cudaGetSymbolAddress((void**)&h1p,  g_h1p);
  cudaGetSymbolAddress((void**)&h3p,  g_h3p);
  cudaGetSymbolAddress((void**)&h4p,  g_h4p);
  cudaGetSymbolAddress((void**)&w1p,  g_W1p);
  cudaGetSymbolAddress((void**)&w2p,  g_W2p);
  cudaGetSymbolAddress((void**)&w4p,  g_W4p);
  cudaGetSymbolAddress((void**)&w5p,  g_W5p);

  const size_t xaP = (size_t)B_SZ * D_SZ;
  const size_t h1P = (size_t)B_SZ * H_SZ;
  const size_t h3P = (size_t)B_SZ * HH;
  const size_t h4P = (size_t)B_SZ * H_SZ;
  const size_t w1P = (size_t)H_SZ * D_SZ;
  const size_t w2P = (size_t)HH * H_SZ;
  const size_t w4P = (size_t)H_SZ * HH;
  const size_t w5P = (size_t)D_SZ * H_SZ;

  // 2-stage pipeline smem: 2 stages * 4 planes * 8KB = 64KB
  const int SMEM = 2 * 4 * 8192;
  cudaFuncSetAttribute(mma_gemm<3,true,2>,  cudaFuncAttributeMaxDynamicSharedMemorySize, SMEM);
  cudaFuncSetAttribute(mma_gemm<3,true,0>,  cudaFuncAttributeMaxDynamicSharedMemorySize, SMEM);
  cudaFuncSetAttribute(mma_gemm<2,true,2>,  cudaFuncAttributeMaxDynamicSharedMemorySize, SMEM);
  cudaFuncSetAttribute(mma_gemm<2,false,0>, cudaFuncAttributeMaxDynamicSharedMemorySize, SMEM);

  // RNG (independent of everything)
  rng_kernel<<<(NROUNDS * B_SZ) / 256, 256>>>(epsb, ub);

  // fp16 splits of inputs / weights
  split8_kernel<<<(unsigned)(xaP / 8 / 256), 256>>>(
      (const float4*)x, (uint4*)xa, (uint4*)(xa + xaP), xaP / 8);
  split8_kernel<<<(unsigned)(w1P / 8 / 256), 256>>>(
      (const float4*)W1, (uint4*)w1p, (uint4*)(w1p + w1P), w1P / 8);
  split8_kernel<<<(unsigned)(w2P / 8 / 256), 256>>>(
      (const float4*)W2, (uint4*)w2p, (uint4*)(w2p + w2P), w2P / 8);
  split8_kernel<<<(unsigned)(w4P / 8 / 256), 256>>>(
      (const float4*)W4, (uint4*)w4p, (uint4*)(w4p + w4P), w4P / 8);
  split8_kernel<<<(unsigned)(w5P / 8 / 256), 256>>>(
      (const float4*)W5, (uint4*)w5p, (uint4*)(w5p + w5P), w5P / 8);

  // encoder: fp16x2 planes, 3 products (~fp32 accuracy)
  mma_gemm<3,true,2><<<dim3(H_SZ/128, B_SZ/128), 256, SMEM>>>(
      xa, xa + xaP, w1p, w1p + w1P,
      b1, nullptr, h1p, h1p + h1P, B_SZ, H_SZ, D_SZ);
  mma_gemm<3,true,0><<<dim3(HH/128, B_SZ/128), 256, SMEM>>>(
      h1p, h1p + h1P, w2p, w2p + w2P,
      b2, h2, nullptr, nullptr, B_SZ, HH, H_SZ);

  // heads
  mukappa_kernel<<<B_SZ / 8, 256>>>(h2, Wmu, bmu, Wk, bk, mu_out, kap_out);

  // sampling
  vmf_z_kernel<<<B_SZ/256, 256>>>(mu_out, kap_out, epsb, ub, zbuf);

  // decoder: GEMM3 SIMT fp32 (K=32) with fused fp16-split epilogue
  sgemm_nt_split<<<dim3(HH/128, B_SZ/128), 256>>>(
      zbuf, W3, b3, h3p, h3p + h3P, B_SZ, HH, L_SZ);

  // decoder: fp16x2 planes, 2 products (error ~1.4e-4 << 1e-3)
  mma_gemm<2,true,2><<<dim3(H_SZ/128, B_SZ/128), 256, SMEM>>>(
      h3p, h3p + h3P, w4p, w4p + w4P,
      b4, nullptr, h4p, h4p + h4P, B_SZ, H_SZ, HH);
  mma_gemm<2,false,0><<<dim3(D_SZ/128, B_SZ/128), 256, SMEM>>>(
      h4p, h4p + h4P, w5p, w5p + w5P,
      b5, x_recon, nullptr, nullptr, B_SZ, D_SZ, H_SZ);
}

// round 17
// speedup vs baseline: 3.1675x; 1.1050x over previous
#include <cuda_runtime.h>
#include <cuda_fp16.h>
#include <cstdint>
#include <cstddef>

#define B_SZ 16384
#define D_SZ 2048
#define H_SZ 1024
#define HH   512
#define L_SZ 32
#define NROUNDS 32

// ---------------- scratch (device globals; no allocation allowed) ----------
__device__ float g_h2[(size_t)B_SZ * HH];     // h2 fp32 (mukappa input)
__device__ float g_z [(size_t)B_SZ * L_SZ];
__device__ float g_eps[(size_t)NROUNDS * B_SZ];
__device__ float g_u [(size_t)NROUNDS * B_SZ];

// fp16 split planes (plane p at offset p*planeElems)
__device__ __half g_xa [2 * (size_t)B_SZ * D_SZ];
__device__ __half g_h1p[2 * (size_t)B_SZ * H_SZ];
__device__ __half g_h3p[2 * (size_t)B_SZ * HH];
__device__ __half g_h4p[2 * (size_t)B_SZ * H_SZ];
__device__ __half g_W1p[2 * (size_t)H_SZ * D_SZ];
__device__ __half g_W2p[2 * (size_t)HH * H_SZ];
__device__ __half g_W4p[2 * (size_t)H_SZ * HH];
__device__ __half g_W5p[2 * (size_t)D_SZ * H_SZ];

// ---------------- JAX threefry2x32 (partitionable semantics) ---------------
__device__ __forceinline__ uint2 tf2x32(uint32_t k0, uint32_t k1,
                                        uint32_t x0, uint32_t x1) {
  uint32_t ks2 = k0 ^ k1 ^ 0x1BD11BDAu;
#define TFR(r) { x0 += x1; x1 = (x1 << (r)) | (x1 >> (32 - (r))); x1 ^= x0; }
  x0 += k0; x1 += k1;
  TFR(13) TFR(15) TFR(26) TFR(6)
  x0 += k1;  x1 += ks2 + 1u;
  TFR(17) TFR(29) TFR(16) TFR(24)
  x0 += ks2; x1 += k0 + 2u;
  TFR(13) TFR(15) TFR(26) TFR(6)
  x0 += k0;  x1 += k1 + 3u;
  TFR(17) TFR(29) TFR(16) TFR(24)
  x0 += k1;  x1 += ks2 + 4u;
  TFR(13) TFR(15) TFR(26) TFR(6)
  x0 += ks2; x1 += k0 + 5u;
#undef TFR
  return make_uint2(x0, x1);
}

__device__ __forceinline__ float u01f(uint32_t bits) {
  return __uint_as_float((bits >> 9) | 0x3f800000u) - 1.0f;
}

__device__ __forceinline__ float xla_erfinv(float x) {
  float t = __fmul_rn(x, x);
  float w = -log1pf(-t);
  float p;
  if (w < 5.0f) {
    w = __fadd_rn(w, -2.5f);
    p = 2.81022636e-08f;
    p = __fadd_rn(3.43273939e-07f, __fmul_rn(p, w));
    p = __fadd_rn(-3.5233877e-06f, __fmul_rn(p, w));
    p = __fadd_rn(-4.39150654e-06f, __fmul_rn(p, w));
    p = __fadd_rn(0.00021858087f, __fmul_rn(p, w));
    p = __fadd_rn(-0.00125372503f, __fmul_rn(p, w));
    p = __fadd_rn(-0.00417768164f, __fmul_rn(p, w));
    p = __fadd_rn(0.246640727f, __fmul_rn(p, w));
    p = __fadd_rn(1.50140941f, __fmul_rn(p, w));
  } else {
    w = __fadd_rn(sqrtf(w), -3.0f);
    p = -0.000200214257f;
    p = __fadd_rn(0.000100950558f, __fmul_rn(p, w));
    p = __fadd_rn(0.00134934322f, __fmul_rn(p, w));
    p = __fadd_rn(-0.00367342844f, __fmul_rn(p, w));
    p = __fadd_rn(0.00573950773f, __fmul_rn(p, w));
    p = __fadd_rn(-0.0076224613f, __fmul_rn(p, w));
    p = __fadd_rn(0.00943887047f, __fmul_rn(p, w));
    p = __fadd_rn(1.00167406f, __fmul_rn(p, w));
    p = __fadd_rn(2.83297682f, __fmul_rn(p, w));
  }
  return __fmul_rn(p, x);
}

__device__ __forceinline__ float jax_normal_from_bits(uint32_t bits) {
  const float lo = -0.99999994f;
  float f = u01f(bits);
  float uu = __fadd_rn(__fmul_rn(f, 2.0f), lo);
  uu = fmaxf(lo, uu);
  return __fmul_rn(1.41421356f, xla_erfinv(uu));
}

__device__ float loggamma15p5(uint2 ekey) {
  const float d = __fadd_rn(15.5f, -0.33333334f);
  const float c = __fdiv_rn(0.33333334f, sqrtf(d));
  uint2 key = tf2x32(ekey.x, ekey.y, 0u, 0u);
  float V = 1.0f;
  for (int it = 0; it < 256; it++) {
    uint2 nk = tf2x32(key.x, key.y, 0u, 0u);
    uint2 xk = tf2x32(key.x, key.y, 0u, 1u);
    uint2 Uk = tf2x32(key.x, key.y, 0u, 2u);
    key = nk;
    float xn = 0.0f, v = -1.0f;
    uint2 kx = xk;
    for (int jt = 0; jt < 256; jt++) {
      uint2 nk2 = tf2x32(kx.x, kx.y, 0u, 0u);
      uint2 sub = tf2x32(kx.x, kx.y, 0u, 1u);
      kx = nk2;
      uint2 ob = tf2x32(sub.x, sub.y, 0u, 0u);
      xn = jax_normal_from_bits(ob.x ^ ob.y);
      v = __fadd_rn(1.0f, __fmul_rn(xn, c));
      if (!(v <= 0.0f)) break;
    }
    float X = __fmul_rn(xn, xn);
    V = __fmul_rn(__fmul_rn(v, v), v);
    uint2 ou = tf2x32(Uk.x, Uk.y, 0u, 0u);
    float U = u01f(ou.x ^ ou.y);
    bool c1 = U >= __fsub_rn(1.0f, __fmul_rn(0.0331f, __fmul_rn(X, X)));
    float rhs = __fadd_rn(__fmul_rn(X, 0.5f),
                          __fmul_rn(d, __fadd_rn(__fsub_rn(1.0f, V), logf(V))));
    bool c2 = logf(U) >= rhs;
    if (!(c1 && c2)) break;
  }
  return __fadd_rn(logf(d), logf(V));
}

__global__ void __launch_bounds__(256)
rng_kernel(float* __restrict__ eps_arr, float* __restrict__ u_arr) {
  int t = blockIdx.x * blockDim.x + threadIdx.x;
  if (t >= NROUNDS * B_SZ) return;
  int r = t >> 14, i = t & 16383;
  uint2 k_rounds = tf2x32(0u, 42u, 0u, 0u);
  uint2 rk = tf2x32(k_rounds.x, k_rounds.y, 0u, (uint32_t)r);
  uint2 k1 = tf2x32(rk.x, rk.y, 0u, 0u);
  uint2 k2 = tf2x32(rk.x, rk.y, 0u, 1u);
  uint2 key_a = tf2x32(k1.x, k1.y, 0u, 0u);
  uint2 key_b = tf2x32(k1.x, k1.y, 0u, 1u);
  uint2 ka = tf2x32(key_a.x, key_a.y, 0u, (uint32_t)i);
  uint2 kb = tf2x32(key_b.x, key_b.y, 0u, (uint32_t)i);
  float lga = loggamma15p5(ka);
  float lgb = loggamma15p5(kb);
  float mx = fmaxf(lga, lgb);
  float ga = expf(__fsub_rn(lga, mx));
  float gb = expf(__fsub_rn(lgb, mx));
  eps_arr[t] = __fdiv_rn(ga, __fadd_rn(ga, gb));
  uint2 ou = tf2x32(k2.x, k2.y, 0u, (uint32_t)i);
  u_arr[t] = u01f(ou.x ^ ou.y);
}

// ---------------- vectorized fp16 split (8 elems / thread) -----------------
__global__ void __launch_bounds__(256)
split8_kernel(const float4* __restrict__ in, uint4* __restrict__ p1,
              uint4* __restrict__ p2, size_t n8) {
  size_t i = (size_t)blockIdx.x * 256 + threadIdx.x;
  if (i >= n8) return;
  float4 a = in[i * 2], b = in[i * 2 + 1];
  float x[8] = {a.x, a.y, a.z, a.w, b.x, b.y, b.z, b.w};
  __align__(16) __half q1[8], q2[8];
#pragma unroll
  for (int c = 0; c < 8; c++) {
    __half h1 = __float2half_rn(x[c]);
    float r1 = x[c] - __half2float(h1);
    q1[c] = h1; q2[c] = __float2half_rn(r1);
  }
  p1[i] = *(uint4*)q1;
  p2[i] = *(uint4*)q2;
}

// ---------------- tensor-core fp16 split GEMM (mma.sync) -------------------
// C[M,N] = act(sum_products A@B^T + bias). A: NPA fp16 planes, B: NPB planes.
// 128x128 CTA tile, 8 warps of 64x32, KC=64, 2-stage cp.async pipeline.
__device__ __forceinline__ void mma16816(float* d, const uint32_t* a,
                                         const uint32_t* b) {
  asm volatile(
      "mma.sync.aligned.m16n8k16.row.col.f32.f16.f16.f32 "
      "{%0,%1,%2,%3},{%4,%5,%6,%7},{%8,%9},{%0,%1,%2,%3};"
      : "+f"(d[0]), "+f"(d[1]), "+f"(d[2]), "+f"(d[3])
      : "r"(a[0]), "r"(a[1]), "r"(a[2]), "r"(a[3]), "r"(b[0]), "r"(b[1]));
}

template <int NPA, int NPB, int NPROD, bool RELU, int NOUT>
__global__ void __launch_bounds__(256, 1)
mma_gemm(const __half* __restrict__ A1, const __half* __restrict__ A2,
         const __half* __restrict__ B1, const __half* __restrict__ B2,
         const float* __restrict__ bias,
         float* __restrict__ Cf,
         __half* __restrict__ O1, __half* __restrict__ O2,
         int M, int N, int K) {
  extern __shared__ char smem[];
  constexpr int PLANES = NPA + NPB;
  constexpr int PLANE_BYTES = 128 * 128;              // 128 rows x 64 fp16 (KC=64)
  constexpr int STAGE_BYTES = PLANES * PLANE_BYTES;
  const int tid = threadIdx.x;
  const int wid = tid >> 5, lane = tid & 31;
  const int wm = wid >> 2, wn = wid & 3;              // 2 x 4 warps
  const int g = lane >> 2, t = lane & 3;
  const int m0 = blockIdx.y << 7, n0 = blockIdx.x << 7;
  const __half* Ap[2] = {A1, A2};
  const __half* Bp[2] = {B1, B2};
  uint32_t sbase = (uint32_t)__cvta_generic_to_shared(smem);

  float acc[4][4][4];
#pragma unroll
  for (int i = 0; i < 4; i++)
#pragma unroll
    for (int j = 0; j < 4; j++)
#pragma unroll
      for (int r = 0; r < 4; r++) acc[i][j][r] = 0.0f;

  const int KT = K >> 6;   // KC = 64

#define ISSUE_STAGE(KT_IDX, STAGE)                                            \
  {                                                                           \
    int k0_ = (KT_IDX) << 6;                                                  \
    _Pragma("unroll")                                                         \
    for (int pl = 0; pl < PLANES; pl++) {                                     \
      const __half* bptr = (pl < NPA) ? Ap[pl] : Bp[pl - NPA];                \
      int roff = (pl < NPA) ? m0 : n0;                                        \
      _Pragma("unroll")                                                       \
      for (int h = 0; h < 4; h++) {                                           \
        int c = tid + h * 256;                                                \
        int row = c >> 3, seg = c & 7;                                        \
        const __half* src =                                                   \
            bptr + (size_t)(roff + row) * K + k0_ + seg * 8;                  \
        uint32_t off = (uint32_t)(row * 128 + seg * 16);                      \
        off ^= (off >> 3) & 0x70;                                             \
        uint32_t dst = sbase + (STAGE) * STAGE_BYTES + pl * PLANE_BYTES + off;\
        asm volatile("cp.async.cg.shared.global [%0], [%1], 16;\n" ::         \
                         "r"(dst), "l"(src));                                 \
      }                                                                       \
    }                                                                         \
  }

  ISSUE_STAGE(0, 0);
  asm volatile("cp.async.commit_group;\n");
  if (KT > 1) ISSUE_STAGE(1, 1);
  asm volatile("cp.async.commit_group;\n");

  // products: NPROD=3 -> A1B1, A1B2, A2B1 (error ~2^-24, fp32-equivalent)
  //           NPROD=2 -> A1B1, A1B2      (error ~2^-12 relative)
  constexpr int PAi[3] = {0, 0, 1};
  constexpr int PBi[3] = {0, 1, 0};

  for (int kt = 0; kt < KT; kt++) {
    asm volatile("cp.async.wait_group 1;\n");
    __syncthreads();
    const int st = kt & 1;
    const uint32_t stb = sbase + st * STAGE_BYTES;
#pragma unroll
    for (int kk = 0; kk < 4; kk++) {
      uint32_t areg[NPA][4][4];
      uint32_t breg[NPB][4][2];
#pragma unroll
      for (int p = 0; p < NPA; p++) {
#pragma unroll
        for (int i = 0; i < 4; i++) {
          int row = wm * 64 + i * 16 + (lane & 15);
          int kb = kk * 32 + ((lane >> 4) << 4);
          uint32_t off = (uint32_t)(row * 128 + kb);
          off ^= (off >> 3) & 0x70;
          uint32_t ad = stb + p * PLANE_BYTES + off;
          asm volatile(
              "ldmatrix.sync.aligned.m8n8.x4.shared.b16 {%0,%1,%2,%3},[%4];"
              : "=r"(areg[p][i][0]), "=r"(areg[p][i][1]),
                "=r"(areg[p][i][2]), "=r"(areg[p][i][3])
              : "r"(ad));
        }
      }
#pragma unroll
      for (int p = 0; p < NPB; p++) {
#pragma unroll
        for (int j = 0; j < 4; j++) {
          int row = wn * 32 + j * 8 + (lane & 7);
          int kb = kk * 32 + (((lane >> 3) & 1) << 4);
          uint32_t off = (uint32_t)(row * 128 + kb);
          off ^= (off >> 3) & 0x70;
          uint32_t ad = stb + (NPA + p) * PLANE_BYTES + off;
          asm volatile(
              "ldmatrix.sync.aligned.m8n8.x2.shared.b16 {%0,%1},[%2];"
              : "=r"(breg[p][j][0]), "=r"(breg[p][j][1])
              : "r"(ad));
        }
      }
#pragma unroll
      for (int p = 0; p < NPROD; p++)
#pragma unroll
        for (int i = 0; i < 4; i++)
#pragma unroll
          for (int j = 0; j < 4; j++)
            mma16816(acc[i][j], areg[PAi[p]][i], breg[PBi[p]][j]);
    }
    __syncthreads();
    if (kt + 2 < KT) ISSUE_STAGE(kt + 2, st);
    asm volatile("cp.async.commit_group;\n");
  }
#undef ISSUE_STAGE

  // epilogue
#pragma unroll
  for (int i = 0; i < 4; i++) {
#pragma unroll
    for (int j = 0; j < 4; j++) {
      int n = n0 + wn * 32 + j * 8 + t * 2;
      int r0 = m0 + wm * 64 + i * 16 + g;
      float bn0 = __ldg(bias + n), bn1 = __ldg(bias + n + 1);
      float v[4];
      v[0] = acc[i][j][0] + bn0; v[1] = acc[i][j][1] + bn1;
      v[2] = acc[i][j][2] + bn0; v[3] = acc[i][j][3] + bn1;
      if (RELU) {
#pragma unroll
        for (int r = 0; r < 4; r++) v[r] = fmaxf(v[r], 0.0f);
      }
      if (NOUT == 0) {
        *(float2*)(Cf + (size_t)r0 * N + n) = make_float2(v[0], v[1]);
        *(float2*)(Cf + (size_t)(r0 + 8) * N + n) = make_float2(v[2], v[3]);
      } else {
#pragma unroll
        for (int half = 0; half < 2; half++) {
          size_t base = (size_t)(r0 + half * 8) * N + n;
          float x0 = v[half * 2], x1 = v[half * 2 + 1];
          __half a0 = __float2half_rn(x0);
          __half a1 = __float2half_rn(x1);
          __half c0 = __float2half_rn(x0 - __half2float(a0));
          __half c1 = __float2half_rn(x1 - __half2float(a1));
          *(__half2*)(O1 + base) = __half2(a0, a1);
          *(__half2*)(O2 + base) = __half2(c0, c1);
        }
      }
    }
  }
}

// ---------------- SIMT SGEMM for K=32 (z@W3), fp16-split epilogue ----------
__global__ void __launch_bounds__(256)
sgemm_nt_split(const float* __restrict__ A, const float* __restrict__ Bw,
               const float* __restrict__ bias,
               __half* __restrict__ O1, __half* __restrict__ O2,
               int M, int N, int K) {
  __shared__ float As[16][132];
  __shared__ float Bs[16][132];
  const int tid = threadIdx.x;
  const int tx = tid & 15, ty = tid >> 4;
  const int m0 = blockIdx.y << 7, n0 = blockIdx.x << 7;
  const float* Ab = A + (size_t)m0 * K;
  const float* Bb = Bw + (size_t)n0 * K;
  const int lrow = tid >> 2;
  const int seg  = tid & 3;
  float acc[8][8];
#pragma unroll
  for (int i = 0; i < 8; i++)
#pragma unroll
    for (int j = 0; j < 8; j++) acc[i][j] = 0.0f;

  for (int k0 = 0; k0 < K; k0 += 16) {
#pragma unroll
    for (int s = 0; s < 2; s++) {
      int r = lrow + s * 64;
      float4 av = *(const float4*)(Ab + (size_t)r * K + k0 + seg * 4);
      As[seg*4+0][r] = av.x; As[seg*4+1][r] = av.y;
      As[seg*4+2][r] = av.z; As[seg*4+3][r] = av.w;
      float4 bv = *(const float4*)(Bb + (size_t)r * K + k0 + seg * 4);
      Bs[seg*4+0][r] = bv.x; Bs[seg*4+1][r] = bv.y;
      Bs[seg*4+2][r] = bv.z; Bs[seg*4+3][r] = bv.w;
    }
    __syncthreads();
#pragma unroll
    for (int kk = 0; kk < 16; kk++) {
      float ar[8], br[8];
#pragma unroll
      for (int i = 0; i < 8; i++) ar[i] = As[kk][ty*8 + i];
#pragma unroll
      for (int j = 0; j < 8; j++) br[j] = Bs[kk][tx*8 + j];
#pragma unroll
      for (int i = 0; i < 8; i++)
#pragma unroll
        for (int j = 0; j < 8; j++)
          acc[i][j] += ar[i] * br[j];
    }
    __syncthreads();
  }
#pragma unroll
  for (int i = 0; i < 8; i++) {
    int m = m0 + ty*8 + i;
    int n = n0 + tx*8;
    __align__(16) __half q1[8], q2[8];
#pragma unroll
    for (int j = 0; j < 8; j++) {
      float v = fmaxf(acc[i][j] + bias[n + j], 0.0f);
      __half h1 = __float2half_rn(v);
      q1[j] = h1; q2[j] = __float2half_rn(v - __half2float(h1));
    }
    size_t base = (size_t)m * N + n;
    *(uint4*)(O1 + base) = *(uint4*)q1;
    *(uint4*)(O2 + base) = *(uint4*)q2;
  }
}

// ---------------- fused mu / kappa head (8 rows per block) ------------------
__global__ void __launch_bounds__(256)
mukappa_kernel(const float* __restrict__ h2, const float* __restrict__ Wmu,
               const float* __restrict__ bmu, const float* __restrict__ Wk,
               const float* __restrict__ bk, float* __restrict__ mu_out,
               float* __restrict__ kap_out) {
  __shared__ float hs[8][HH];
  __shared__ float wrow[HH];
  __shared__ float outv[8][33];
  const int r0 = blockIdx.x * 8;
  const int tid = threadIdx.x;
  const int wid = tid >> 5, lane = tid & 31;
#pragma unroll
  for (int q = 0; q < 4; q++) {
    int idx = tid + q * 256;
    int row = idx >> 7, c4 = idx & 127;
    ((float4*)hs[row])[c4] = ((const float4*)(h2 + (size_t)(r0 + row) * HH))[c4];
  }
  __syncthreads();
  for (int j = 0; j < 33; j++) {
    const float* wr = (j < 32) ? (Wmu + (size_t)j * HH) : Wk;
    if (tid < 128) ((float4*)wrow)[tid] = ((const float4*)wr)[tid];
    __syncthreads();
    float s = 0.0f;
#pragma unroll 4
    for (int t = lane; t < HH; t += 32) s += hs[wid][t] * wrow[t];
#pragma unroll
    for (int off = 16; off; off >>= 1) s += __shfl_down_sync(0xffffffffu, s, off);
    if (lane == 0) outv[wid][j] = s + ((j < 32) ? bmu[j] : bk[0]);
    __syncthreads();
  }
  {
    float m = outv[wid][lane];
    float ss = m * m;
#pragma unroll
    for (int off = 16; off; off >>= 1) ss += __shfl_xor_sync(0xffffffffu, ss, off);
    float nf = sqrtf(ss) + 1e-8f;
    mu_out[(size_t)(r0 + wid) * 32 + lane] = m / nf;
    if (lane == 0) {
      float xx = outv[wid][32];
      float sp = fmaxf(xx, 0.0f) + log1pf(expf(-fabsf(xx)));
      kap_out[r0 + wid] = sp + 1.0f;
    }
  }
}

// ---------------- vMF: Wood scan + tangent normals + Householder -----------
__global__ void __launch_bounds__(256)
vmf_z_kernel(const float* __restrict__ mu, const float* __restrict__ kap,
             const float* __restrict__ eps_arr, const float* __restrict__ u_arr,
             float* __restrict__ z) {
  int i = blockIdx.x * blockDim.x + threadIdx.x;
  if (i >= B_SZ) return;
  float k = kap[i];
  float sq = sqrtf(__fadd_rn(__fmul_rn(__fmul_rn(4.0f, k), k), 961.0f));
  float b  = __fdiv_rn(__fadd_rn(__fmul_rn(-2.0f, k), sq), 31.0f);
  float a  = __fdiv_rn(__fadd_rn(__fadd_rn(31.0f, __fmul_rn(2.0f, k)), sq), 4.0f);
  float d  = __fsub_rn(__fdiv_rn(__fmul_rn(__fmul_rn(4.0f, a), b), __fadd_rn(1.0f, b)),
                       __fmul_rn(31.0f, logf(31.0f)));
  float omb = __fsub_rn(1.0f, b), opb = __fadd_rn(1.0f, b);
  float ab2 = __fmul_rn(__fmul_rn(2.0f, a), b);
  float w = 0.0f; bool acc = false;
  for (int r = 0; r < NROUNDS; r++) {
    float eps = eps_arr[r * B_SZ + i];
    float u   = u_arr[r * B_SZ + i];
    float denom = __fsub_rn(1.0f, __fmul_rn(omb, eps));
    float wp = __fdiv_rn(__fsub_rn(1.0f, __fmul_rn(opb, eps)), denom);
    float t  = __fdiv_rn(ab2, denom);
    bool ok = __fadd_rn(__fsub_rn(__fmul_rn(31.0f, logf(t)), t), d)
              >= logf(__fadd_rn(u, 1e-20f));
    w = acc ? w : wp;
    acc = acc || ok;
  }
  w = fminf(fmaxf(w, -0.99999988f), 0.99999988f);

  uint2 kt = tf2x32(0u, 42u, 0u, 1u);
  float v[31]; float ss = 0.0f;
#pragma unroll
  for (int j = 0; j < 31; j++) {
    uint2 o = tf2x32(kt.x, kt.y, 0u, (uint32_t)(i * 31 + j));
    float xn = jax_normal_from_bits(o.x ^ o.y);
    v[j] = xn; ss += xn * xn;
  }
  float nf = sqrtf(ss) + 1e-12f;
  float s = sqrtf(__fsub_rn(1.0f, __fmul_rn(w, w)));

  const float* mrow = mu + (size_t)i * 32;
  float mloc[32];
#pragma unroll
  for (int c = 0; c < 32; c++) mloc[c] = mrow[c];
  float un2 = 0.0f;
#pragma unroll
  for (int c = 0; c < 32; c++) {
    float uh = ((c == 0) ? 1.0f : 0.0f) - mloc[c];
    un2 += uh * uh;
  }
  float unf = sqrtf(un2) + 1e-8f;
  float dot = 0.0f;
#pragma unroll
  for (int c = 0; c < 32; c++) {
    float ze = (c == 0) ? w : s * (v[c - 1] / nf);
    float uh = (((c == 0) ? 1.0f : 0.0f) - mloc[c]) / unf;
    dot += ze * uh;
  }
  float td = 2.0f * dot;
#pragma unroll
  for (int c = 0; c < 32; c++) {
    float ze = (c == 0) ? w : s * (v[c - 1] / nf);
    float uh = (((c == 0) ? 1.0f : 0.0f) - mloc[c]) / unf;
    z[(size_t)i * 32 + c] = ze - td * uh;
  }
}

// ---------------- launch ----------------------------------------------------
extern "C" void kernel_launch(void* const* d_in, const int* in_sizes, int n_in,
                              void* d_out, int out_size) {
  const float* x   = (const float*)d_in[0];
  const float* W1  = (const float*)d_in[1];
  const float* b1  = (const float*)d_in[2];
  const float* W2  = (const float*)d_in[3];
  const float* b2  = (const float*)d_in[4];
  const float* Wmu = (const float*)d_in[5];
  const float* bmu = (const float*)d_in[6];
  const float* Wk  = (const float*)d_in[7];
  const float* bk  = (const float*)d_in[8];
  const float* W3  = (const float*)d_in[9];
  const float* b3  = (const float*)d_in[10];
  const float* W4  = (const float*)d_in[11];
  const float* b4  = (const float*)d_in[12];
  const float* W5  = (const float*)d_in[13];
  const float* b5  = (const float*)d_in[14];

  float* out = (float*)d_out;
  float* x_recon = out;
  float* mu_out  = out + (size_t)B_SZ * D_SZ;
  float* kap_out = mu_out + (size_t)B_SZ * L_SZ;

  float *h2, *zbuf, *epsb, *ub;
  __half *xa, *h1p, *h3p, *h4p, *w1p, *w2p, *w4p, *w5p;
  cudaGetSymbolAddress((void**)&h2,   g_h2);
  cudaGetSymbolAddress((void**)&zbuf, g_z);
  cudaGetSymbolAddress((void**)&epsb, g_eps);
  cudaGetSymbolAddress((void**)&ub,   g_u);
  cudaGetSymbolAddress((void**)&xa,   g_xa);
  cudaGetSymbolAddress((void**)&h1p,  g_h1p);
  cudaGetSymbolAddress((void**)&h3p,  g_h3p);
  cudaGetSymbolAddress((void**)&h4p,  g_h4p);
  cudaGetSymbolAddress((void**)&w1p,  g_W1p);
  cudaGetSymbolAddress((void**)&w2p,  g_W2p);
  cudaGetSymbolAddress((void**)&w4p,  g_W4p);
  cudaGetSymbolAddress((void**)&w5p,  g_W5p);

  const size_t xaP = (size_t)B_SZ * D_SZ;
  const size_t h1P = (size_t)B_SZ * H_SZ;
  const size_t h3P = (size_t)B_SZ * HH;
  const size_t h4P = (size_t)B_SZ * H_SZ;
  const size_t w1P = (size_t)H_SZ * D_SZ;
  const size_t w2P = (size_t)HH * H_SZ;
  const size_t w4P = (size_t)H_SZ * HH;
  const size_t w5P = (size_t)D_SZ * H_SZ;

  // KC=64: stage = planes * 16KB; 2 stages
  const int SMEM_ENC = 2 * 4 * 16384;   // 131072 (NPA=2,NPB=2)
  const int SMEM_DEC = 2 * 3 * 16384;   // 98304  (NPA=1,NPB=2)
  cudaFuncSetAttribute(mma_gemm<2,2,3,true,2>,  cudaFuncAttributeMaxDynamicSharedMemorySize, SMEM_ENC);
  cudaFuncSetAttribute(mma_gemm<2,2,3,true,0>,  cudaFuncAttributeMaxDynamicSharedMemorySize, SMEM_ENC);
  cudaFuncSetAttribute(mma_gemm<1,2,2,true,2>,  cudaFuncAttributeMaxDynamicSharedMemorySize, SMEM_DEC);
  cudaFuncSetAttribute(mma_gemm<1,2,2,false,0>, cudaFuncAttributeMaxDynamicSharedMemorySize, SMEM_DEC);

  // RNG (independent of everything)
  rng_kernel<<<(NROUNDS * B_SZ) / 256, 256>>>(epsb, ub);

  // fp16 splits of inputs / weights
  split8_kernel<<<(unsigned)(xaP / 8 / 256), 256>>>(
      (const float4*)x, (uint4*)xa, (uint4*)(xa + xaP), xaP / 8);
  split8_kernel<<<(unsigned)(w1P / 8 / 256), 256>>>(
      (const float4*)W1, (uint4*)w1p, (uint4*)(w1p + w1P), w1P / 8);
  split8_kernel<<<(unsigned)(w2P / 8 / 256), 256>>>(
      (const float4*)W2, (uint4*)w2p, (uint4*)(w2p + w2P), w2P / 8);
  split8_kernel<<<(unsigned)(w4P / 8 / 256), 256>>>(
      (const float4*)W4, (uint4*)w4p, (uint4*)(w4p + w4P), w4P / 8);
  split8_kernel<<<(unsigned)(w5P / 8 / 256), 256>>>(
      (const float4*)W5, (uint4*)w5p, (uint4*)(w5p + w5P), w5P / 8);

  // encoder: fp16x2 planes, 3 products (~fp32 accuracy)
  mma_gemm<2,2,3,true,2><<<dim3(H_SZ/128, B_SZ/128), 256, SMEM_ENC>>>(
      xa, xa + xaP, w1p, w1p + w1P,
      b1, nullptr, h1p, h1p + h1P, B_SZ, H_SZ, D_SZ);
  mma_gemm<2,2,3,true,0><<<dim3(HH/128, B_SZ/128), 256, SMEM_ENC>>>(
      h1p, h1p + h1P, w2p, w2p + w2P,
      b2, h2, nullptr, nullptr, B_SZ, HH, H_SZ);

  // heads
  mukappa_kernel<<<B_SZ / 8, 256>>>(h2, Wmu, bmu, Wk, bk, mu_out, kap_out);

  // sampling
  vmf_z_kernel<<<B_SZ/256, 256>>>(mu_out, kap_out, epsb, ub, zbuf);

  // decoder: GEMM3 SIMT fp32 (K=32) with fused fp16-split epilogue
  sgemm_nt_split<<<dim3(HH/128, B_SZ/128), 256>>>(
      zbuf, W3, b3, h3p, h3p + h3P, B_SZ, HH, L_SZ);

  // decoder: fp16 A-plane1 only, 2 products (A1B1 + A1B2)
  mma_gemm<1,2,2,true,2><<<dim3(H_SZ/128, B_SZ/128), 256, SMEM_DEC>>>(
      h3p, nullptr, w4p, w4p + w4P,
      b4, nullptr, h4p, h4p + h4P, B_SZ, H_SZ, HH);
  mma_gemm<1,2,2,false,0><<<dim3(D_SZ/128, B_SZ/128), 256, SMEM_DEC>>>(
      h4p, nullptr, w5p, w5p + w5P,
      b5, x_recon, nullptr, nullptr, B_SZ, D_SZ, H_SZ);
}